// round 2
// baseline (speedup 1.0000x reference)
#include <cuda_runtime.h>
#include <math.h>

#define BATCH 512
#define NCAM  6
#define NID   751
#define DIM   2048
#define CN    (NCAM*NID)    /* 4506 */
#define BC    (BATCH*NCAM)  /* 3072 */

// ---------------- scratch (device globals; no allocation allowed) ----------
__device__ float g_F[BATCH*DIM];          // normalized features
__device__ float g_A[CN*DIM];             // normalized cross anchors
__device__ float g_L[BATCH*CN];           // logits
__device__ float g_logZ[BC];
__device__ unsigned long long g_rank_key[BC];
__device__ unsigned long long g_back_key[BC];
__device__ int   g_rank_idx[BC];
__device__ float g_score[BC];
__device__ float g_coef_cross[BC];
__device__ float g_coef_self[BATCH];
__device__ int   g_qidx[BATCH];
__device__ int   g_cam[BATCH];
__device__ int   g_lab[BATCH];
__device__ int   g_tasks[NCAM*BC];
__device__ int   g_cnt[NCAM];
__device__ float g_loss;

// ---------------- helpers --------------------------------------------------
__device__ __forceinline__ unsigned fenc(float f){
    unsigned u = __float_as_uint(f);
    return (u & 0x80000000u) ? ~u : (u | 0x80000000u);
}
__device__ __forceinline__ float fdec(unsigned e){
    unsigned u = (e & 0x80000000u) ? (e ^ 0x80000000u) : ~e;
    return __uint_as_float(u);
}
// scalar inputs may arrive as int32 or float32; small-int bit pattern disambiguates
__device__ __forceinline__ int scal_int(const void* p){
    int v = *(const int*)p;
    if (v > -1000000 && v < 1000000) return v;
    return (int)(*(const float*)p);
}
__device__ __forceinline__ float scal_float(const void* p){
    int v = *(const int*)p;
    if (v > -1000000 && v < 1000000) return (float)v;
    return *(const float*)p;
}

// ---------------- normalization -------------------------------------------
// which==0 -> write g_F, which==1 -> write g_A
__global__ __launch_bounds__(256) void k_norm(const float* __restrict__ in, int which){
    int row = blockIdx.x;
    int tid = threadIdx.x;
    const float4* ip = (const float4*)(in + (size_t)row*DIM);
    float4 a = ip[tid], b = ip[tid+256];
    float ss = a.x*a.x+a.y*a.y+a.z*a.z+a.w*a.w
             + b.x*b.x+b.y*b.y+b.z*b.z+b.w*b.w;
    __shared__ float red[8];
    #pragma unroll
    for(int o=16;o;o>>=1) ss += __shfl_xor_sync(0xffffffffu, ss, o);
    if((tid&31)==0) red[tid>>5]=ss;
    __syncthreads();
    float tot = red[0]+red[1]+red[2]+red[3]+red[4]+red[5]+red[6]+red[7];
    float s = 1.0f/(sqrtf(tot)+1e-12f);
    float* out = which ? g_A : g_F;
    float4* op = (float4*)(out + (size_t)row*DIM);
    a.x*=s;a.y*=s;a.z*=s;a.w*=s; b.x*=s;b.y*=s;b.z*=s;b.w*=s;
    op[tid]=a; op[tid+256]=b;
}

// ---------------- init / task build ----------------------------------------
__global__ void k_init(){
    int i = blockIdx.x*256 + threadIdx.x;
    if(i < BC){ g_rank_key[i]=0ull; g_back_key[i]=0ull; }
    if(i < NCAM) g_cnt[i]=0;
    if(i == 0) g_loss = 0.0f;
}
__global__ void k_build(const int* __restrict__ labels, const int* __restrict__ cams){
    int b = blockIdx.x*256 + threadIdx.x;
    if(b >= BATCH) return;
    int cam = cams[b]-1, lab = labels[b]-1;
    g_cam[b]=cam; g_lab[b]=lab;
    g_qidx[b]=cam*NID+lab;
    int pos = atomicAdd(&g_cnt[cam], NCAM);
    #pragma unroll
    for(int c=0;c<NCAM;c++) g_tasks[cam*BC + pos + c] = b*NCAM + c;
}

// ---------------- main GEMM: logits (by<4) + rank rows (by>=4) -------------
// output tile 128x128, threads 256, per-thread 8x8, BK=8
__global__ __launch_bounds__(256) void k_gemm_main(){
    __shared__ float As[8][132];
    __shared__ float Bs[8][132];
    __shared__ const float* Arow[128];
    __shared__ int Brow[128];
    __shared__ unsigned long long sred[128][2];

    int tid=threadIdx.x, bx=blockIdx.x, by=blockIdx.y;
    bool rankmode = (by >= 4);
    if(tid < 128){
        int r = by*128 + tid;
        Arow[tid] = rankmode ? (g_A + (size_t)g_qidx[r-512]*DIM)
                             : (g_F + (size_t)r*DIM);
        sred[tid][0]=0ull; sred[tid][1]=0ull;
    } else {
        int c = bx*128 + (tid-128);
        Brow[tid-128] = (c < CN) ? c : (CN-1);
    }
    __syncthreads();

    int lr = tid>>1, lk=(tid&1)*4;
    const float* aptr = Arow[lr] + lk;
    const float* bptr = g_A + (size_t)Brow[lr]*DIM + lk;
    int tx = tid&15, ty = tid>>4;

    float acc[8][8];
    #pragma unroll
    for(int i=0;i<8;i++)
        #pragma unroll
        for(int j=0;j<8;j++) acc[i][j]=0.0f;

    for(int k0=0;k0<DIM;k0+=8){
        float4 av = *(const float4*)(aptr + k0);
        float4 bv = *(const float4*)(bptr + k0);
        __syncthreads();
        As[lk+0][lr]=av.x; As[lk+1][lr]=av.y; As[lk+2][lr]=av.z; As[lk+3][lr]=av.w;
        Bs[lk+0][lr]=bv.x; Bs[lk+1][lr]=bv.y; Bs[lk+2][lr]=bv.z; Bs[lk+3][lr]=bv.w;
        __syncthreads();
        #pragma unroll
        for(int kk=0;kk<8;kk++){
            float a[8], b[8];
            *(float4*)(a)   = *(const float4*)&As[kk][ty*4];
            *(float4*)(a+4) = *(const float4*)&As[kk][64+ty*4];
            *(float4*)(b)   = *(const float4*)&Bs[kk][tx*4];
            *(float4*)(b+4) = *(const float4*)&Bs[kk][64+tx*4];
            #pragma unroll
            for(int i=0;i<8;i++)
                #pragma unroll
                for(int j=0;j<8;j++)
                    acc[i][j] += a[i]*b[j];
        }
    }

    int rows[8], cols[8];
    #pragma unroll
    for(int i=0;i<4;i++){ rows[i]=ty*4+i; rows[i+4]=64+ty*4+i; }
    #pragma unroll
    for(int j=0;j<4;j++){ cols[j]=tx*4+j; cols[j+4]=64+tx*4+j; }

    if(!rankmode){
        #pragma unroll
        for(int i=0;i<8;i++){
            int gr = by*128 + rows[i];
            #pragma unroll
            for(int j=0;j<8;j++){
                int gc = bx*128 + cols[j];
                if(gc < CN) g_L[(size_t)gr*CN + gc] = acc[i][j];
            }
        }
    } else {
        int c0 = (bx*128)/NID;
        #pragma unroll
        for(int i=0;i<8;i++){
            unsigned long long b0=0ull, b1=0ull;
            #pragma unroll
            for(int j=0;j<8;j++){
                int gc = bx*128 + cols[j];
                if(gc < CN){
                    int c = gc/NID; int m = gc - c*NID;
                    unsigned long long key = ((unsigned long long)fenc(acc[i][j])<<32)
                                           | (unsigned)(0xFFFFFFFFu - (unsigned)m);
                    if(c==c0){ if(key>b0) b0=key; } else { if(key>b1) b1=key; }
                }
            }
            if(b0) atomicMax(&sred[rows[i]][0], b0);
            if(b1) atomicMax(&sred[rows[i]][1], b1);
        }
        __syncthreads();
        {
            int row = tid>>1, slot = tid&1;
            int c = c0 + slot;
            unsigned long long v = sred[row][slot];
            if(c < NCAM && v){
                int b = (by-4)*128 + row;
                atomicMax(&g_rank_key[b*NCAM + c], v);
            }
        }
    }
}

__global__ void k_rank_extract(){
    int t = blockIdx.x*256 + threadIdx.x;
    if(t >= BC) return;
    unsigned long long key = g_rank_key[t];
    g_rank_idx[t] = (int)(0xFFFFFFFFu - (unsigned)(key & 0xFFFFFFFFull));
    g_score[t]    = fdec((unsigned)(key>>32));
}

// ---------------- back GEMM: column argmax at rank columns ------------------
__global__ __launch_bounds__(256) void k_gemm_back(){
    __shared__ float As[8][132];
    __shared__ float Bs[8][132];
    __shared__ const float* Arow[128];
    __shared__ int Brow[128];
    __shared__ int Btask[128];
    __shared__ unsigned long long sred[128];

    int icam = blockIdx.z;
    int cnt  = g_cnt[icam];
    int tb   = blockIdx.y*128;
    if(tb >= cnt) return;
    int rb   = blockIdx.x*128;

    int tid = threadIdx.x;
    if(tid < 128){
        int n = rb + tid; if(n > NID-1) n = NID-1;
        Arow[tid] = g_A + (size_t)(icam*NID + n)*DIM;
        sred[tid] = 0ull;
    } else {
        int k = tid-128;
        int tt = tb + k;
        int tcl = (tt < cnt) ? tt : (cnt-1);
        int t = g_tasks[icam*BC + tcl];
        Btask[k] = (tt < cnt) ? t : -1;
        int c = t % NCAM;
        Brow[k] = c*NID + g_rank_idx[t];
    }
    __syncthreads();

    int lr = tid>>1, lk=(tid&1)*4;
    const float* aptr = Arow[lr] + lk;
    const float* bptr = g_A + (size_t)Brow[lr]*DIM + lk;
    int tx = tid&15, ty = tid>>4;

    float acc[8][8];
    #pragma unroll
    for(int i=0;i<8;i++)
        #pragma unroll
        for(int j=0;j<8;j++) acc[i][j]=0.0f;

    for(int k0=0;k0<DIM;k0+=8){
        float4 av = *(const float4*)(aptr + k0);
        float4 bv = *(const float4*)(bptr + k0);
        __syncthreads();
        As[lk+0][lr]=av.x; As[lk+1][lr]=av.y; As[lk+2][lr]=av.z; As[lk+3][lr]=av.w;
        Bs[lk+0][lr]=bv.x; Bs[lk+1][lr]=bv.y; Bs[lk+2][lr]=bv.z; Bs[lk+3][lr]=bv.w;
        __syncthreads();
        #pragma unroll
        for(int kk=0;kk<8;kk++){
            float a[8], b[8];
            *(float4*)(a)   = *(const float4*)&As[kk][ty*4];
            *(float4*)(a+4) = *(const float4*)&As[kk][64+ty*4];
            *(float4*)(b)   = *(const float4*)&Bs[kk][tx*4];
            *(float4*)(b+4) = *(const float4*)&Bs[kk][64+tx*4];
            #pragma unroll
            for(int i=0;i<8;i++)
                #pragma unroll
                for(int j=0;j<8;j++)
                    acc[i][j] += a[i]*b[j];
        }
    }

    int rows[8], cols[8];
    #pragma unroll
    for(int i=0;i<4;i++){ rows[i]=ty*4+i; rows[i+4]=64+ty*4+i; }
    #pragma unroll
    for(int j=0;j<4;j++){ cols[j]=tx*4+j; cols[j+4]=64+tx*4+j; }

    #pragma unroll
    for(int j=0;j<8;j++){
        unsigned long long best = 0ull;
        #pragma unroll
        for(int i=0;i<8;i++){
            int n = rb + rows[i];
            if(n < NID){
                unsigned long long key = ((unsigned long long)fenc(acc[i][j])<<32)
                                       | (unsigned)(0xFFFFFFFFu - (unsigned)n);
                if(key > best) best = key;
            }
        }
        if(best) atomicMax(&sred[cols[j]], best);
    }
    __syncthreads();
    if(tid < 128){
        int t = Btask[tid];
        if(t >= 0 && sred[tid]) atomicMax(&g_back_key[t], sred[tid]);
    }
}

// ---------------- logsumexp -------------------------------------------------
__global__ __launch_bounds__(128) void k_logZ_kernel(){
    int t = blockIdx.x;
    const float* p = g_L + (size_t)(t/NCAM)*CN + (size_t)(t%NCAM)*NID;
    int tid = threadIdx.x;
    float mx = -1e30f;
    for(int i=tid;i<NID;i+=128) mx = fmaxf(mx, p[i]);
    __shared__ float red[4];
    __shared__ float red2[4];
    #pragma unroll
    for(int o=16;o;o>>=1) mx = fmaxf(mx, __shfl_xor_sync(0xffffffffu,mx,o));
    if((tid&31)==0) red[tid>>5]=mx;
    __syncthreads();
    mx = fmaxf(fmaxf(red[0],red[1]),fmaxf(red[2],red[3]));
    float s = 0.0f;
    for(int i=tid;i<NID;i+=128) s += expf(p[i]-mx);
    #pragma unroll
    for(int o=16;o;o>>=1) s += __shfl_xor_sync(0xffffffffu,s,o);
    if((tid&31)==0) red2[tid>>5]=s;
    __syncthreads();
    if(tid==0) g_logZ[t] = mx + logf(red2[0]+red2[1]+red2[2]+red2[3]);
}

// ---------------- coefficients + loss --------------------------------------
__global__ void k_coef(const void* lrp){
    int b = blockIdx.x*256 + threadIdx.x;
    if(b >= BATCH) return;
    float lrf = scal_float(lrp);
    int cam = g_cam[b], lab = g_lab[b];
    float lsum = 0.0f;
    #pragma unroll
    for(int c=0;c<NCAM;c++){
        int t = b*NCAM + c;
        float lz = g_logZ[t];
        int r    = g_rank_idx[t];
        float sc = g_score[t];
        float ce = lz - g_L[(size_t)b*CN + c*NID + r];
        int backi = (int)(0xFFFFFFFFu - (unsigned)(g_back_key[t] & 0xFFFFFFFFull));
        bool valid = (backi==lab) && (sc > 0.5f) && (c != cam);
        float w = valid ? sc : 0.0f;
        g_coef_cross[t] = w * lrf * (1.0f - ce);
        lsum += w * ce;
        if(c == cam){
            float ces = lz - g_L[(size_t)b*CN + c*NID + lab];
            g_coef_self[b] = lrf * (1.0f - ces);
            lsum += ces;
        }
    }
    atomicAdd(&g_loss, lsum);
}

// ---------------- output base: copy A (epoch>10) or normalize(intra) --------
// NOTE: out+1 is only 4-byte aligned -> destination stores MUST be scalar.
__global__ __launch_bounds__(256) void k_write_base(const float* __restrict__ intra,
                                                    const void* epp,
                                                    float* __restrict__ out){
    int row = blockIdx.x;
    int tid = threadIdx.x;
    int ep = scal_int(epp);
    float* dst = out + 1 + (size_t)row*DIM;
    if(ep <= 10){
        const float4* ip = (const float4*)(intra + (size_t)row*DIM);
        float4 a = ip[tid], b = ip[tid+256];
        float ss = a.x*a.x+a.y*a.y+a.z*a.z+a.w*a.w
                 + b.x*b.x+b.y*b.y+b.z*b.z+b.w*b.w;
        __shared__ float red[8];
        #pragma unroll
        for(int o=16;o;o>>=1) ss += __shfl_xor_sync(0xffffffffu, ss, o);
        if((tid&31)==0) red[tid>>5]=ss;
        __syncthreads();
        float tot = red[0]+red[1]+red[2]+red[3]+red[4]+red[5]+red[6]+red[7];
        float s = 1.0f/(sqrtf(tot)+1e-12f);
        // scalar stores (coalesced 4B): lane-contiguous layout
        dst[tid*4+0]=a.x*s; dst[tid*4+1]=a.y*s; dst[tid*4+2]=a.z*s; dst[tid*4+3]=a.w*s;
        dst[1024+tid*4+0]=b.x*s; dst[1024+tid*4+1]=b.y*s; dst[1024+tid*4+2]=b.z*s; dst[1024+tid*4+3]=b.w*s;
    } else {
        const float* src = g_A + (size_t)row*DIM;
        #pragma unroll
        for(int it=0; it<8; it++){
            int d = tid + it*256;
            dst[d] = src[d];
        }
    }
}

// ---------------- scatter update -------------------------------------------
__global__ __launch_bounds__(256) void k_scatter(const void* epp, float* __restrict__ out){
    int ep = scal_int(epp);
    if(ep <= 10) return;
    int b = blockIdx.x, j = blockIdx.y;
    float coef; int row;
    if(j == NCAM){ coef = g_coef_self[b]; row = g_qidx[b]; }
    else { int t = b*NCAM + j; coef = g_coef_cross[t]; row = j*NID + g_rank_idx[t]; }
    if(coef == 0.0f) return;   // adding exact zero is a no-op; skip the atomics
    const float* f = g_F + (size_t)b*DIM;
    float* dst = out + 1 + (size_t)row*DIM;
    for(int d=threadIdx.x; d<DIM; d+=256)
        atomicAdd(&dst[d], -coef * f[d]);
}

__global__ void k_loss(const void* epp, float* out){
    int ep = scal_int(epp);
    out[0] = (ep > 10) ? (g_loss / (float)BATCH) : 0.0f;
}

// ---------------- launch ----------------------------------------------------
extern "C" void kernel_launch(void* const* d_in, const int* in_sizes, int n_in,
                              void* d_out, int out_size){
    const float* features = (const float*)d_in[0];
    const int*   labels   = (const int*)  d_in[1];
    const int*   cams     = (const int*)  d_in[2];
    const float* intra    = (const float*)d_in[3];
    const float* cross    = (const float*)d_in[4];
    const void*  epp      = d_in[5];
    const void*  lrp      = d_in[6];
    float* out = (float*)d_out;

    k_norm<<<BATCH, 256>>>(features, 0);
    k_norm<<<CN,    256>>>(cross,    1);
    k_init<<<(BC+255)/256, 256>>>();
    k_build<<<(BATCH+255)/256, 256>>>(labels, cams);

    // logits (by 0..3) + rank rows (by 4..7): cols = 4506 -> 36 tiles of 128
    k_gemm_main<<<dim3(36, 8), 256>>>();
    k_rank_extract<<<(BC+255)/256, 256>>>();

    // back columns: rows 751 -> 6 tiles, tasks up to 3072 -> 24 tiles, z = cam
    k_gemm_back<<<dim3(6, 24, NCAM), 256>>>();

    k_logZ_kernel<<<BC, 128>>>();
    k_coef<<<(BATCH+255)/256, 256>>>(lrp);

    k_write_base<<<CN, 256>>>(intra, epp, out);
    k_scatter<<<dim3(BATCH, NCAM+1), 256>>>(epp, out);
    k_loss<<<1, 1>>>(epp, out);
}

// round 3
// speedup vs baseline: 5.0932x; 5.0932x over previous
#include <cuda_runtime.h>
#include <cuda_bf16.h>
#include <math.h>

#define BATCH 512
#define NCAM  6
#define NID   751
#define DIM   2048
#define D2    (DIM/2)       /* 1024 packed bf16x2 */
#define CN    (NCAM*NID)    /* 4506 */
#define BC    (BATCH*NCAM)  /* 3072 */

// ---------------- scratch (device globals; no allocation allowed) ----------
__device__ float    g_F[BATCH*DIM];       // normalized features (fp32)
__device__ float    g_A[CN*DIM];          // normalized cross anchors (fp32)
__device__ unsigned g_Fh[BATCH*D2];       // packed bf16x2
__device__ unsigned g_Ah[CN*D2];          // packed bf16x2
__device__ float    g_L[BATCH*CN];        // logits
__device__ float    g_logZ[BC];
__device__ unsigned long long g_rank_key[BC];
__device__ unsigned long long g_back_key[BC];
__device__ int   g_rank_idx[BC];
__device__ float g_score[BC];
__device__ float g_coef_cross[BC];
__device__ float g_coef_self[BATCH];
__device__ int   g_qidx[BATCH];
__device__ int   g_cam[BATCH];
__device__ int   g_lab[BATCH];
__device__ int   g_tasks[NCAM*BC];
__device__ int   g_cnt[NCAM];
__device__ float g_loss;

// ---------------- helpers --------------------------------------------------
__device__ __forceinline__ unsigned fenc(float f){
    unsigned u = __float_as_uint(f);
    return (u & 0x80000000u) ? ~u : (u | 0x80000000u);
}
__device__ __forceinline__ float fdec(unsigned e){
    unsigned u = (e & 0x80000000u) ? (e ^ 0x80000000u) : ~e;
    return __uint_as_float(u);
}
__device__ __forceinline__ int scal_int(const void* p){
    int v = *(const int*)p;
    if (v > -1000000 && v < 1000000) return v;
    return (int)(*(const float*)p);
}
__device__ __forceinline__ float scal_float(const void* p){
    int v = *(const int*)p;
    if (v > -1000000 && v < 1000000) return (float)v;
    return *(const float*)p;
}
__device__ __forceinline__ unsigned pack_bf2(float x, float y){
    __nv_bfloat162 h = __floats2bfloat162_rn(x, y);
    return *(unsigned*)&h;   // .x (x) in low half
}

// ---------------- normalization: fp32 out + packed bf16 out ----------------
// which==0 -> g_F/g_Fh, which==1 -> g_A/g_Ah
__global__ __launch_bounds__(256) void k_norm(const float* __restrict__ in, int which){
    int row = blockIdx.x;
    int tid = threadIdx.x;
    const float4* ip = (const float4*)(in + (size_t)row*DIM);
    float4 a = ip[tid], b = ip[tid+256];
    float ss = a.x*a.x+a.y*a.y+a.z*a.z+a.w*a.w
             + b.x*b.x+b.y*b.y+b.z*b.z+b.w*b.w;
    __shared__ float red[8];
    #pragma unroll
    for(int o=16;o;o>>=1) ss += __shfl_xor_sync(0xffffffffu, ss, o);
    if((tid&31)==0) red[tid>>5]=ss;
    __syncthreads();
    float tot = red[0]+red[1]+red[2]+red[3]+red[4]+red[5]+red[6]+red[7];
    float s = 1.0f/(sqrtf(tot)+1e-12f);
    float*    out  = which ? g_A  : g_F;
    unsigned* outh = which ? g_Ah : g_Fh;
    float4* op = (float4*)(out + (size_t)row*DIM);
    a.x*=s;a.y*=s;a.z*=s;a.w*=s; b.x*=s;b.y*=s;b.z*=s;b.w*=s;
    op[tid]=a; op[tid+256]=b;
    unsigned* hp = outh + (size_t)row*D2;
    hp[tid*2+0]     = pack_bf2(a.x,a.y);
    hp[tid*2+1]     = pack_bf2(a.z,a.w);
    hp[512+tid*2+0] = pack_bf2(b.x,b.y);
    hp[512+tid*2+1] = pack_bf2(b.z,b.w);
}

// ---------------- init / sample meta ---------------------------------------
__global__ void k_init(){
    int i = blockIdx.x*256 + threadIdx.x;
    if(i < BC){ g_rank_key[i]=0ull; g_back_key[i]=0ull; }
    if(i < NCAM) g_cnt[i]=0;
    if(i == 0) g_loss = 0.0f;
}
__global__ void k_build(const int* __restrict__ labels, const int* __restrict__ cams){
    int b = blockIdx.x*256 + threadIdx.x;
    if(b >= BATCH) return;
    int cam = cams[b]-1, lab = labels[b]-1;
    g_cam[b]=cam; g_lab[b]=lab;
    g_qidx[b]=cam*NID+lab;
}

// ---------------- main GEMM (bf16 mma): logits (by<4) + rank (by>=4) -------
// block tile 128x128, 8 warps (4x2), warp tile 32x64, BK = 32 halves
__global__ __launch_bounds__(256,2) void k_gemm_main(){
    __shared__ unsigned As2[16][136];
    __shared__ unsigned Bs2[16][136];
    __shared__ const unsigned* Arowp[128];
    __shared__ const unsigned* Browp[128];
    __shared__ unsigned long long sred[128][2];

    int tid=threadIdx.x, bx=blockIdx.x, by=blockIdx.y;
    bool rankmode = (by >= 4);
    if(tid < 128){
        int r = by*128 + tid;
        Arowp[tid] = rankmode ? (g_Ah + (size_t)g_qidx[r-512]*D2)
                              : (g_Fh + (size_t)r*D2);
        sred[tid][0]=0ull; sred[tid][1]=0ull;
    } else {
        int c = bx*128 + (tid-128);
        Browp[tid-128] = g_Ah + (size_t)((c<CN)?c:(CN-1))*D2;
    }
    __syncthreads();

    int lane = tid & 31, w = tid >> 5;
    int wm = w >> 1, wn = w & 1;          // 4 x 2 warp grid
    int g = lane >> 2, tig = lane & 3;
    int lr = tid >> 1, h = tid & 1;
    const unsigned* ap = Arowp[lr] + h*8;
    const unsigned* bp = Browp[lr] + h*8;
    int kb = h*8;

    float acc[2][8][4];
    #pragma unroll
    for(int mi=0;mi<2;mi++)
        #pragma unroll
        for(int ni=0;ni<8;ni++)
            #pragma unroll
            for(int q=0;q<4;q++) acc[mi][ni][q]=0.0f;

    for(int k2=0; k2<D2; k2+=16){
        uint4 av0 = *(const uint4*)(ap + k2);
        uint4 av1 = *(const uint4*)(ap + k2 + 4);
        uint4 bv0 = *(const uint4*)(bp + k2);
        uint4 bv1 = *(const uint4*)(bp + k2 + 4);
        __syncthreads();
        As2[kb+0][lr]=av0.x; As2[kb+1][lr]=av0.y; As2[kb+2][lr]=av0.z; As2[kb+3][lr]=av0.w;
        As2[kb+4][lr]=av1.x; As2[kb+5][lr]=av1.y; As2[kb+6][lr]=av1.z; As2[kb+7][lr]=av1.w;
        Bs2[kb+0][lr]=bv0.x; Bs2[kb+1][lr]=bv0.y; Bs2[kb+2][lr]=bv0.z; Bs2[kb+3][lr]=bv0.w;
        Bs2[kb+4][lr]=bv1.x; Bs2[kb+5][lr]=bv1.y; Bs2[kb+6][lr]=bv1.z; Bs2[kb+7][lr]=bv1.w;
        __syncthreads();
        #pragma unroll
        for(int ks=0; ks<16; ks+=8){
            unsigned af[2][4], bf[8][2];
            #pragma unroll
            for(int mi=0;mi<2;mi++){
                int m0 = wm*32 + mi*16;
                af[mi][0] = As2[ks+tig  ][m0+g];
                af[mi][1] = As2[ks+tig  ][m0+8+g];
                af[mi][2] = As2[ks+tig+4][m0+g];
                af[mi][3] = As2[ks+tig+4][m0+8+g];
            }
            #pragma unroll
            for(int ni=0;ni<8;ni++){
                int n0 = wn*64 + ni*8;
                bf[ni][0] = Bs2[ks+tig  ][n0+g];
                bf[ni][1] = Bs2[ks+tig+4][n0+g];
            }
            #pragma unroll
            for(int mi=0;mi<2;mi++)
                #pragma unroll
                for(int ni=0;ni<8;ni++){
                    asm volatile(
                        "mma.sync.aligned.m16n8k16.row.col.f32.bf16.bf16.f32 "
                        "{%0,%1,%2,%3}, {%4,%5,%6,%7}, {%8,%9}, {%0,%1,%2,%3};"
                        : "+f"(acc[mi][ni][0]), "+f"(acc[mi][ni][1]),
                          "+f"(acc[mi][ni][2]), "+f"(acc[mi][ni][3])
                        : "r"(af[mi][0]),"r"(af[mi][1]),"r"(af[mi][2]),"r"(af[mi][3]),
                          "r"(bf[ni][0]),"r"(bf[ni][1]));
                }
        }
    }

    if(!rankmode){
        #pragma unroll
        for(int mi=0;mi<2;mi++){
            int r0 = by*128 + wm*32 + mi*16 + g;
            #pragma unroll
            for(int ni=0;ni<8;ni++){
                int col = bx*128 + wn*64 + ni*8 + tig*2;
                if(col+1 < CN){
                    *(float2*)&g_L[(size_t)r0*CN + col]     = make_float2(acc[mi][ni][0], acc[mi][ni][1]);
                    *(float2*)&g_L[(size_t)(r0+8)*CN + col] = make_float2(acc[mi][ni][2], acc[mi][ni][3]);
                } else if(col < CN){
                    g_L[(size_t)r0*CN + col]     = acc[mi][ni][0];
                    g_L[(size_t)(r0+8)*CN + col] = acc[mi][ni][2];
                }
            }
        }
    } else {
        int c0 = (bx*128)/NID;
        #pragma unroll
        for(int mi=0;mi<2;mi++){
            int row0 = wm*32 + mi*16 + g;   // local row (and row0+8)
            unsigned long long best[2][2] = {{0ull,0ull},{0ull,0ull}};
            #pragma unroll
            for(int ni=0;ni<8;ni++){
                int colb = bx*128 + wn*64 + ni*8 + tig*2;
                #pragma unroll
                for(int q=0;q<2;q++){
                    int gc = colb + q;
                    if(gc < CN){
                        int c = gc/NID, m = gc - c*NID;
                        int slot = (c==c0) ? 0 : 1;
                        unsigned long long k0 =
                            ((unsigned long long)fenc(acc[mi][ni][q])<<32)
                          | (unsigned)(0xFFFFFFFFu - (unsigned)m);
                        unsigned long long k1 =
                            ((unsigned long long)fenc(acc[mi][ni][2+q])<<32)
                          | (unsigned)(0xFFFFFFFFu - (unsigned)m);
                        if(k0 > best[0][slot]) best[0][slot] = k0;
                        if(k1 > best[1][slot]) best[1][slot] = k1;
                    }
                }
            }
            #pragma unroll
            for(int rh=0;rh<2;rh++)
                #pragma unroll
                for(int slot=0;slot<2;slot++)
                    if(best[rh][slot]) atomicMax(&sred[row0+rh*8][slot], best[rh][slot]);
        }
        __syncthreads();
        {
            int row = tid>>1, slot = tid&1;
            int c = c0 + slot;
            unsigned long long v = sred[row][slot];
            if(c < NCAM && v){
                int b = (by-4)*128 + row;
                atomicMax(&g_rank_key[b*NCAM + c], v);
            }
        }
    }
}

__global__ void k_rank_extract(){
    int t = blockIdx.x*256 + threadIdx.x;
    if(t >= BC) return;
    unsigned long long key = g_rank_key[t];
    g_rank_idx[t] = (int)(0xFFFFFFFFu - (unsigned)(key & 0xFFFFFFFFull));
    g_score[t]    = fdec((unsigned)(key>>32));
}

// ---------------- filtered task list: back needed only if score>0.5 & c!=cam
__global__ void k_build_tasks(){
    int t = blockIdx.x*256 + threadIdx.x;
    if(t >= BC) return;
    int b = t/NCAM, c = t - b*NCAM;
    int cam = g_cam[b];
    if(c == cam) return;
    if(!(g_score[t] > 0.5f)) return;
    int pos = atomicAdd(&g_cnt[cam], 1);
    g_tasks[cam*BC + pos] = t;
}

// ---------------- back GEMM (fp32 FFMA; normally empty -> instant exit) ----
__global__ __launch_bounds__(256) void k_gemm_back(){
    __shared__ float As[8][132];
    __shared__ float Bs[8][132];
    __shared__ const float* Arow[128];
    __shared__ int Brow[128];
    __shared__ int Btask[128];
    __shared__ unsigned long long sred[128];

    int icam = blockIdx.z;
    int cnt  = g_cnt[icam];
    int tb   = blockIdx.y*128;
    if(tb >= cnt) return;
    int rb   = blockIdx.x*128;

    int tid = threadIdx.x;
    if(tid < 128){
        int n = rb + tid; if(n > NID-1) n = NID-1;
        Arow[tid] = g_A + (size_t)(icam*NID + n)*DIM;
        sred[tid] = 0ull;
    } else {
        int k = tid-128;
        int tt = tb + k;
        int tcl = (tt < cnt) ? tt : (cnt-1);
        int t = g_tasks[icam*BC + tcl];
        Btask[k] = (tt < cnt) ? t : -1;
        int c = t % NCAM;
        Brow[k] = c*NID + g_rank_idx[t];
    }
    __syncthreads();

    int lr = tid>>1, lk=(tid&1)*4;
    const float* aptr = Arow[lr] + lk;
    const float* bptr = g_A + (size_t)Brow[lr]*DIM + lk;
    int tx = tid&15, ty = tid>>4;

    float acc[8][8];
    #pragma unroll
    for(int i=0;i<8;i++)
        #pragma unroll
        for(int j=0;j<8;j++) acc[i][j]=0.0f;

    for(int k0=0;k0<DIM;k0+=8){
        float4 av = *(const float4*)(aptr + k0);
        float4 bv = *(const float4*)(bptr + k0);
        __syncthreads();
        As[lk+0][lr]=av.x; As[lk+1][lr]=av.y; As[lk+2][lr]=av.z; As[lk+3][lr]=av.w;
        Bs[lk+0][lr]=bv.x; Bs[lk+1][lr]=bv.y; Bs[lk+2][lr]=bv.z; Bs[lk+3][lr]=bv.w;
        __syncthreads();
        #pragma unroll
        for(int kk=0;kk<8;kk++){
            float a[8], b[8];
            *(float4*)(a)   = *(const float4*)&As[kk][ty*4];
            *(float4*)(a+4) = *(const float4*)&As[kk][64+ty*4];
            *(float4*)(b)   = *(const float4*)&Bs[kk][tx*4];
            *(float4*)(b+4) = *(const float4*)&Bs[kk][64+tx*4];
            #pragma unroll
            for(int i=0;i<8;i++)
                #pragma unroll
                for(int j=0;j<8;j++)
                    acc[i][j] += a[i]*b[j];
        }
    }

    int rows[8], cols[8];
    #pragma unroll
    for(int i=0;i<4;i++){ rows[i]=ty*4+i; rows[i+4]=64+ty*4+i; }
    #pragma unroll
    for(int j=0;j<4;j++){ cols[j]=tx*4+j; cols[j+4]=64+tx*4+j; }

    #pragma unroll
    for(int j=0;j<8;j++){
        unsigned long long best = 0ull;
        #pragma unroll
        for(int i=0;i<8;i++){
            int n = rb + rows[i];
            if(n < NID){
                unsigned long long key = ((unsigned long long)fenc(acc[i][j])<<32)
                                       | (unsigned)(0xFFFFFFFFu - (unsigned)n);
                if(key > best) best = key;
            }
        }
        if(best) atomicMax(&sred[cols[j]], best);
    }
    __syncthreads();
    if(tid < 128){
        int t = Btask[tid];
        if(t >= 0 && sred[tid]) atomicMax(&g_back_key[t], sred[tid]);
    }
}

// ---------------- logsumexp -------------------------------------------------
__global__ __launch_bounds__(128) void k_logZ_kernel(){
    int t = blockIdx.x;
    const float* p = g_L + (size_t)(t/NCAM)*CN + (size_t)(t%NCAM)*NID;
    int tid = threadIdx.x;
    float mx = -1e30f;
    for(int i=tid;i<NID;i+=128) mx = fmaxf(mx, p[i]);
    __shared__ float red[4];
    __shared__ float red2[4];
    #pragma unroll
    for(int o=16;o;o>>=1) mx = fmaxf(mx, __shfl_xor_sync(0xffffffffu,mx,o));
    if((tid&31)==0) red[tid>>5]=mx;
    __syncthreads();
    mx = fmaxf(fmaxf(red[0],red[1]),fmaxf(red[2],red[3]));
    float s = 0.0f;
    for(int i=tid;i<NID;i+=128) s += expf(p[i]-mx);
    #pragma unroll
    for(int o=16;o;o>>=1) s += __shfl_xor_sync(0xffffffffu,s,o);
    if((tid&31)==0) red2[tid>>5]=s;
    __syncthreads();
    if(tid==0) g_logZ[t] = mx + logf(red2[0]+red2[1]+red2[2]+red2[3]);
}

// ---------------- coefficients + loss --------------------------------------
__global__ void k_coef(const void* lrp){
    int b = blockIdx.x*256 + threadIdx.x;
    if(b >= BATCH) return;
    float lrf = scal_float(lrp);
    int cam = g_cam[b], lab = g_lab[b];
    float lsum = 0.0f;
    #pragma unroll
    for(int c=0;c<NCAM;c++){
        int t = b*NCAM + c;
        float lz = g_logZ[t];
        int r    = g_rank_idx[t];
        float sc = g_score[t];
        float ce = lz - g_L[(size_t)b*CN + c*NID + r];
        int backi = (int)(0xFFFFFFFFu - (unsigned)(g_back_key[t] & 0xFFFFFFFFull));
        bool valid = (backi==lab) && (sc > 0.5f) && (c != cam);
        float w = valid ? sc : 0.0f;
        g_coef_cross[t] = w * lrf * (1.0f - ce);
        lsum += w * ce;
        if(c == cam){
            float ces = lz - g_L[(size_t)b*CN + c*NID + lab];
            g_coef_self[b] = lrf * (1.0f - ces);
            lsum += ces;
        }
    }
    atomicAdd(&g_loss, lsum);
}

// ---------------- output base (out+1 is only 4B aligned: scalar stores) -----
__global__ __launch_bounds__(256) void k_write_base(const float* __restrict__ intra,
                                                    const void* epp,
                                                    float* __restrict__ out){
    int row = blockIdx.x;
    int tid = threadIdx.x;
    int ep = scal_int(epp);
    float* dst = out + 1 + (size_t)row*DIM;
    if(ep <= 10){
        const float4* ip = (const float4*)(intra + (size_t)row*DIM);
        float4 a = ip[tid], b = ip[tid+256];
        float ss = a.x*a.x+a.y*a.y+a.z*a.z+a.w*a.w
                 + b.x*b.x+b.y*b.y+b.z*b.z+b.w*b.w;
        __shared__ float red[8];
        #pragma unroll
        for(int o=16;o;o>>=1) ss += __shfl_xor_sync(0xffffffffu, ss, o);
        if((tid&31)==0) red[tid>>5]=ss;
        __syncthreads();
        float tot = red[0]+red[1]+red[2]+red[3]+red[4]+red[5]+red[6]+red[7];
        float s = 1.0f/(sqrtf(tot)+1e-12f);
        dst[tid*4+0]=a.x*s; dst[tid*4+1]=a.y*s; dst[tid*4+2]=a.z*s; dst[tid*4+3]=a.w*s;
        dst[1024+tid*4+0]=b.x*s; dst[1024+tid*4+1]=b.y*s; dst[1024+tid*4+2]=b.z*s; dst[1024+tid*4+3]=b.w*s;
    } else {
        const float* src = g_A + (size_t)row*DIM;
        #pragma unroll
        for(int it=0; it<8; it++){
            int d = tid + it*256;
            dst[d] = src[d];
        }
    }
}

// ---------------- scatter update -------------------------------------------
__global__ __launch_bounds__(256) void k_scatter(const void* epp, float* __restrict__ out){
    int ep = scal_int(epp);
    if(ep <= 10) return;
    int b = blockIdx.x, j = blockIdx.y;
    float coef; int row;
    if(j == NCAM){ coef = g_coef_self[b]; row = g_qidx[b]; }
    else { int t = b*NCAM + j; coef = g_coef_cross[t]; row = j*NID + g_rank_idx[t]; }
    if(coef == 0.0f) return;
    const float* f = g_F + (size_t)b*DIM;
    float* dst = out + 1 + (size_t)row*DIM;
    for(int d=threadIdx.x; d<DIM; d+=256)
        atomicAdd(&dst[d], -coef * f[d]);
}

__global__ void k_loss(const void* epp, float* out){
    int ep = scal_int(epp);
    out[0] = (ep > 10) ? (g_loss / (float)BATCH) : 0.0f;
}

// ---------------- launch ----------------------------------------------------
extern "C" void kernel_launch(void* const* d_in, const int* in_sizes, int n_in,
                              void* d_out, int out_size){
    const float* features = (const float*)d_in[0];
    const int*   labels   = (const int*)  d_in[1];
    const int*   cams     = (const int*)  d_in[2];
    const float* intra    = (const float*)d_in[3];
    const float* cross    = (const float*)d_in[4];
    const void*  epp      = d_in[5];
    const void*  lrp      = d_in[6];
    float* out = (float*)d_out;

    k_norm<<<BATCH, 256>>>(features, 0);
    k_norm<<<CN,    256>>>(cross,    1);
    k_init<<<(BC+255)/256, 256>>>();
    k_build<<<(BATCH+255)/256, 256>>>(labels, cams);

    // logits (by 0..3) + rank rows (by 4..7); cols 4506 -> 36 tiles of 128
    k_gemm_main<<<dim3(36, 8), 256>>>();
    k_rank_extract<<<(BC+255)/256, 256>>>();
    k_build_tasks<<<(BC+255)/256, 256>>>();

    // back columns: only runs if some score > 0.5 (filtered tasks)
    k_gemm_back<<<dim3(6, 24, NCAM), 256>>>();

    k_logZ_kernel<<<BC, 128>>>();
    k_coef<<<(BATCH+255)/256, 256>>>(lrp);

    k_write_base<<<CN, 256>>>(intra, epp, out);
    k_scatter<<<dim3(BATCH, NCAM+1), 256>>>(epp, out);
    k_loss<<<1, 1>>>(epp, out);
}

// round 4
// speedup vs baseline: 7.3647x; 1.4460x over previous
#include <cuda_runtime.h>
#include <cuda_bf16.h>
#include <math.h>

#define BATCH 512
#define NCAM  6
#define NID   751
#define DIM   2048
#define D2    (DIM/2)       /* 1024 packed bf16x2 words per row */
#define CN    (NCAM*NID)    /* 4506 */
#define BC    (BATCH*NCAM)  /* 3072 */
#define NK    (D2/16)       /* 64 k-blocks of 16 words (32 halves) */

// ---------------- scratch (device globals; no allocation allowed) ----------
__device__ float    g_F[BATCH*DIM];       // normalized features (fp32, for scatter)
__device__ unsigned g_Fh[BATCH*D2];       // packed bf16x2, K-permuted
__device__ unsigned g_Ah[CN*D2];          // packed bf16x2, K-permuted
__device__ float    g_L[BATCH*CN];        // logits
__device__ float    g_logZ[BC];
__device__ unsigned long long g_rank_key[BC];
__device__ unsigned long long g_back_key[BC];
__device__ int   g_rank_idx[BC];
__device__ float g_score[BC];
__device__ float g_coef_cross[BC];
__device__ float g_coef_self[BATCH];
__device__ int   g_qidx[BATCH];
__device__ int   g_cam[BATCH];
__device__ int   g_lab[BATCH];
__device__ int   g_tasks[NCAM*BC];
__device__ int   g_cnt[NCAM];
__device__ float g_loss;

// ---------------- helpers --------------------------------------------------
__device__ __forceinline__ unsigned fenc(float f){
    unsigned u = __float_as_uint(f);
    return (u & 0x80000000u) ? ~u : (u | 0x80000000u);
}
__device__ __forceinline__ float fdec(unsigned e){
    unsigned u = (e & 0x80000000u) ? (e ^ 0x80000000u) : ~e;
    return __uint_as_float(u);
}
__device__ __forceinline__ int scal_int(const void* p){
    int v = *(const int*)p;
    if (v > -1000000 && v < 1000000) return v;
    return (int)(*(const float*)p);
}
__device__ __forceinline__ float scal_float(const void* p){
    int v = *(const int*)p;
    if (v > -1000000 && v < 1000000) return (float)v;
    return *(const float*)p;
}
__device__ __forceinline__ unsigned pack_bf2(float x, float y){
    __nv_bfloat162 h = __floats2bfloat162_rn(x, y);
    return *(unsigned*)&h;
}
// K-permutation inside each 16-word chunk: makes thread fragment words contiguous
__device__ __forceinline__ int permk2(int K){
    return (K & ~15) | ((K & 3) << 2) | ((K >> 2) & 3);
}
__device__ __forceinline__ void cpasync16(unsigned saddr, const void* g){
    asm volatile("cp.async.cg.shared.global [%0], [%1], 16;" :: "r"(saddr), "l"(g));
}

// ---------------- normalization -------------------------------------------
__global__ __launch_bounds__(256) void k_norm_feat(const float* __restrict__ in){
    int row = blockIdx.x;
    int tid = threadIdx.x;
    const float4* ip = (const float4*)(in + (size_t)row*DIM);
    float4 a = ip[tid], b = ip[tid+256];
    float ss = a.x*a.x+a.y*a.y+a.z*a.z+a.w*a.w
             + b.x*b.x+b.y*b.y+b.z*b.z+b.w*b.w;
    __shared__ float red[8];
    #pragma unroll
    for(int o=16;o;o>>=1) ss += __shfl_xor_sync(0xffffffffu, ss, o);
    if((tid&31)==0) red[tid>>5]=ss;
    __syncthreads();
    float tot = red[0]+red[1]+red[2]+red[3]+red[4]+red[5]+red[6]+red[7];
    float s = 1.0f/(sqrtf(tot)+1e-12f);
    a.x*=s;a.y*=s;a.z*=s;a.w*=s; b.x*=s;b.y*=s;b.z*=s;b.w*=s;
    float4* op = (float4*)(g_F + (size_t)row*DIM);
    op[tid]=a; op[tid+256]=b;
    unsigned* hp = g_Fh + (size_t)row*D2;
    hp[permk2(2*tid  )]     = pack_bf2(a.x,a.y);
    hp[permk2(2*tid+1)]     = pack_bf2(a.z,a.w);
    hp[permk2(512+2*tid  )] = pack_bf2(b.x,b.y);
    hp[permk2(512+2*tid+1)] = pack_bf2(b.z,b.w);
}

// cross anchors: packed bf16 + (if epoch>10) write output base directly
__global__ __launch_bounds__(256) void k_norm_cross(const float* __restrict__ in,
                                                    const void* epp,
                                                    float* __restrict__ out){
    int row = blockIdx.x;
    int tid = threadIdx.x;
    const float4* ip = (const float4*)(in + (size_t)row*DIM);
    float4 a = ip[tid], b = ip[tid+256];
    float ss = a.x*a.x+a.y*a.y+a.z*a.z+a.w*a.w
             + b.x*b.x+b.y*b.y+b.z*b.z+b.w*b.w;
    __shared__ float red[8];
    #pragma unroll
    for(int o=16;o;o>>=1) ss += __shfl_xor_sync(0xffffffffu, ss, o);
    if((tid&31)==0) red[tid>>5]=ss;
    __syncthreads();
    float tot = red[0]+red[1]+red[2]+red[3]+red[4]+red[5]+red[6]+red[7];
    float s = 1.0f/(sqrtf(tot)+1e-12f);
    a.x*=s;a.y*=s;a.z*=s;a.w*=s; b.x*=s;b.y*=s;b.z*=s;b.w*=s;
    unsigned* hp = g_Ah + (size_t)row*D2;
    hp[permk2(2*tid  )]     = pack_bf2(a.x,a.y);
    hp[permk2(2*tid+1)]     = pack_bf2(a.z,a.w);
    hp[permk2(512+2*tid  )] = pack_bf2(b.x,b.y);
    hp[permk2(512+2*tid+1)] = pack_bf2(b.z,b.w);
    if(scal_int(epp) > 10){
        // out+1 is only 4B aligned -> scalar stores
        float* dst = out + 1 + (size_t)row*DIM;
        dst[tid*4+0]=a.x; dst[tid*4+1]=a.y; dst[tid*4+2]=a.z; dst[tid*4+3]=a.w;
        dst[1024+tid*4+0]=b.x; dst[1024+tid*4+1]=b.y; dst[1024+tid*4+2]=b.z; dst[1024+tid*4+3]=b.w;
    }
}

// warm-up output path (epoch<=10): out = normalize(intra)
__global__ __launch_bounds__(256) void k_warm_base(const float* __restrict__ intra,
                                                   const void* epp,
                                                   float* __restrict__ out){
    if(scal_int(epp) > 10) return;
    int row = blockIdx.x;
    int tid = threadIdx.x;
    const float4* ip = (const float4*)(intra + (size_t)row*DIM);
    float4 a = ip[tid], b = ip[tid+256];
    float ss = a.x*a.x+a.y*a.y+a.z*a.z+a.w*a.w
             + b.x*b.x+b.y*b.y+b.z*b.z+b.w*b.w;
    __shared__ float red[8];
    #pragma unroll
    for(int o=16;o;o>>=1) ss += __shfl_xor_sync(0xffffffffu, ss, o);
    if((tid&31)==0) red[tid>>5]=ss;
    __syncthreads();
    float tot = red[0]+red[1]+red[2]+red[3]+red[4]+red[5]+red[6]+red[7];
    float s = 1.0f/(sqrtf(tot)+1e-12f);
    float* dst = out + 1 + (size_t)row*DIM;
    dst[tid*4+0]=a.x*s; dst[tid*4+1]=a.y*s; dst[tid*4+2]=a.z*s; dst[tid*4+3]=a.w*s;
    dst[1024+tid*4+0]=b.x*s; dst[1024+tid*4+1]=b.y*s; dst[1024+tid*4+2]=b.z*s; dst[1024+tid*4+3]=b.w*s;
}

// ---------------- setup: init + sample meta (merged) ------------------------
__global__ void k_setup(const int* __restrict__ labels, const int* __restrict__ cams){
    int i = blockIdx.x*256 + threadIdx.x;
    if(i < BC){ g_rank_key[i]=0ull; g_back_key[i]=0ull; }
    if(i < NCAM) g_cnt[i]=0;
    if(i == 0) g_loss = 0.0f;
    if(i < BATCH){
        int cam = cams[i]-1, lab = labels[i]-1;
        g_cam[i]=cam; g_lab[i]=lab;
        g_qidx[i]=cam*NID+lab;
    }
}

// ---------------- main GEMM (bf16 mma, cp.async double-buffered) ------------
// block tile 128x128, 8 warps (4x2), warp tile 32x64; smem rows of 16 words
#define MMA_OP(ACC,A0,A1,A2,A3,B0,B1) \
    asm volatile("mma.sync.aligned.m16n8k16.row.col.f32.bf16.bf16.f32 " \
        "{%0,%1,%2,%3}, {%4,%5,%6,%7}, {%8,%9}, {%0,%1,%2,%3};" \
        : "+f"((ACC)[0]), "+f"((ACC)[1]), "+f"((ACC)[2]), "+f"((ACC)[3]) \
        : "r"(A0),"r"(A1),"r"(A2),"r"(A3),"r"(B0),"r"(B1))

__global__ __launch_bounds__(256,2) void k_gemm_main(){
    __shared__ unsigned As[2][2048];    // [buf][row*16 + word]
    __shared__ unsigned Bs[2][2048];
    __shared__ const unsigned* Arowp[128];
    __shared__ const unsigned* Browp[128];
    __shared__ unsigned long long sred[128][2];

    int tid=threadIdx.x, bx=blockIdx.x, by=blockIdx.y;
    bool rankmode = (by >= 4);
    if(tid < 128){
        int r = by*128 + tid;
        Arowp[tid] = rankmode ? (g_Ah + (size_t)g_qidx[r-512]*D2)
                              : (g_Fh + (size_t)r*D2);
        sred[tid][0]=0ull; sred[tid][1]=0ull;
    } else {
        int c = bx*128 + (tid-128);
        Browp[tid-128] = g_Ah + (size_t)((c<CN)?c:(CN-1))*D2;
    }
    __syncthreads();

    int lane = tid & 31, w = tid >> 5;
    int wm = w >> 1, wn = w & 1;
    int g = lane >> 2, tig = lane & 3;
    int m0 = wm*32, n0 = wn*64;

    // per-thread prefetch lanes: 2 A rows + 2 B rows, one 16B seg each
    int prow = tid >> 2, pseg = tid & 3;
    const unsigned* gA0 = Arowp[prow]    + pseg*4;
    const unsigned* gA1 = Arowp[prow+64] + pseg*4;
    const unsigned* gB0 = Browp[prow]    + pseg*4;
    const unsigned* gB1 = Browp[prow+64] + pseg*4;
    unsigned off0 = (unsigned)((prow*16 + pseg*4)*4);
    unsigned off1 = (unsigned)(((prow+64)*16 + pseg*4)*4);
    unsigned sbA = (unsigned)__cvta_generic_to_shared(&As[0][0]);
    unsigned sbB = (unsigned)__cvta_generic_to_shared(&Bs[0][0]);

    float acc[2][8][4];
    #pragma unroll
    for(int mi=0;mi<2;mi++)
        #pragma unroll
        for(int ni=0;ni<8;ni++)
            #pragma unroll
            for(int q=0;q<4;q++) acc[mi][ni][q]=0.0f;

    // prefetch k-block 0 into buffer 0
    {
        cpasync16(sbA + off0, gA0);
        cpasync16(sbA + off1, gA1);
        cpasync16(sbB + off0, gB0);
        cpasync16(sbB + off1, gB1);
        asm volatile("cp.async.commit_group;" ::: "memory");
    }

    for(int kb=0; kb<NK; kb++){
        int s = kb & 1;
        if(kb+1 < NK){
            unsigned bo = (unsigned)(((kb+1)&1)*8192);
            int ko = (kb+1)*16;
            cpasync16(sbA + bo + off0, gA0 + ko);
            cpasync16(sbA + bo + off1, gA1 + ko);
            cpasync16(sbB + bo + off0, gB0 + ko);
            cpasync16(sbB + bo + off1, gB1 + ko);
        }
        asm volatile("cp.async.commit_group;" ::: "memory");
        asm volatile("cp.async.wait_group 1;" ::: "memory");
        __syncthreads();

        const unsigned* as  = As[s];
        const unsigned* bsp = Bs[s];

        uint4 a_lo[2], a_hi[2];
        #pragma unroll
        for(int mi=0;mi<2;mi++){
            a_lo[mi] = *(const uint4*)(as + (m0 + mi*16 + g)*16 + tig*4);
            a_hi[mi] = *(const uint4*)(as + (m0 + mi*16 + 8 + g)*16 + tig*4);
        }
        #pragma unroll
        for(int nh=0; nh<2; nh++){
            uint4 bf[4];
            #pragma unroll
            for(int nj=0;nj<4;nj++)
                bf[nj] = *(const uint4*)(bsp + (n0 + (nh*4+nj)*8 + g)*16 + tig*4);
            #pragma unroll
            for(int mi=0;mi<2;mi++)
                #pragma unroll
                for(int nj=0;nj<4;nj++){
                    int ni = nh*4+nj;
                    MMA_OP(acc[mi][ni], a_lo[mi].x, a_hi[mi].x, a_lo[mi].y, a_hi[mi].y,
                                        bf[nj].x, bf[nj].y);
                    MMA_OP(acc[mi][ni], a_lo[mi].z, a_hi[mi].z, a_lo[mi].w, a_hi[mi].w,
                                        bf[nj].z, bf[nj].w);
                }
        }
        __syncthreads();
    }

    if(!rankmode){
        #pragma unroll
        for(int mi=0;mi<2;mi++){
            int r0 = by*128 + m0 + mi*16 + g;
            #pragma unroll
            for(int ni=0;ni<8;ni++){
                int col = bx*128 + n0 + ni*8 + tig*2;
                if(col+1 < CN){
                    *(float2*)&g_L[(size_t)r0*CN + col]     = make_float2(acc[mi][ni][0], acc[mi][ni][1]);
                    *(float2*)&g_L[(size_t)(r0+8)*CN + col] = make_float2(acc[mi][ni][2], acc[mi][ni][3]);
                } else if(col < CN){
                    g_L[(size_t)r0*CN + col]     = acc[mi][ni][0];
                    g_L[(size_t)(r0+8)*CN + col] = acc[mi][ni][2];
                }
            }
        }
    } else {
        int c0 = (bx*128)/NID;
        #pragma unroll
        for(int mi=0;mi<2;mi++){
            int row0 = m0 + mi*16 + g;
            unsigned long long best[2][2] = {{0ull,0ull},{0ull,0ull}};
            #pragma unroll
            for(int ni=0;ni<8;ni++){
                int colb = bx*128 + n0 + ni*8 + tig*2;
                #pragma unroll
                for(int q=0;q<2;q++){
                    int gc = colb + q;
                    if(gc < CN){
                        int c = gc/NID, m = gc - c*NID;
                        int slot = (c==c0) ? 0 : 1;
                        unsigned long long k0 =
                            ((unsigned long long)fenc(acc[mi][ni][q])<<32)
                          | (unsigned)(0xFFFFFFFFu - (unsigned)m);
                        unsigned long long k1 =
                            ((unsigned long long)fenc(acc[mi][ni][2+q])<<32)
                          | (unsigned)(0xFFFFFFFFu - (unsigned)m);
                        if(k0 > best[0][slot]) best[0][slot] = k0;
                        if(k1 > best[1][slot]) best[1][slot] = k1;
                    }
                }
            }
            #pragma unroll
            for(int rh=0;rh<2;rh++)
                #pragma unroll
                for(int slot=0;slot<2;slot++)
                    if(best[rh][slot]) atomicMax(&sred[row0+rh*8][slot], best[rh][slot]);
        }
        __syncthreads();
        {
            int row = tid>>1, slot = tid&1;
            int c = c0 + slot;
            unsigned long long v = sred[row][slot];
            if(c < NCAM && v){
                int b = (by-4)*128 + row;
                atomicMax(&g_rank_key[b*NCAM + c], v);
            }
        }
    }
}

// ---------------- rank extract + filtered task build (merged) ---------------
__global__ void k_rank_tasks(){
    int t = blockIdx.x*256 + threadIdx.x;
    if(t >= BC) return;
    unsigned long long key = g_rank_key[t];
    int   ridx = (int)(0xFFFFFFFFu - (unsigned)(key & 0xFFFFFFFFull));
    float sc   = fdec((unsigned)(key>>32));
    g_rank_idx[t] = ridx;
    g_score[t]    = sc;
    int b = t/NCAM, c = t - b*NCAM;
    int cam = g_cam[b];
    if(c != cam && sc > 0.5f){
        int pos = atomicAdd(&g_cnt[cam], 1);
        g_tasks[cam*BC + pos] = t;
    }
}

// ---------------- back GEMM (bf16 unpack + FFMA; normally empty) ------------
__global__ __launch_bounds__(256) void k_gemm_back(){
    __shared__ unsigned As2[8][132];
    __shared__ unsigned Bs2[8][132];
    __shared__ const unsigned* Arow[128];
    __shared__ const unsigned* Brow[128];
    __shared__ int Btask[128];
    __shared__ unsigned long long sred[128];

    int icam = blockIdx.z;
    int cnt  = g_cnt[icam];
    int tb   = blockIdx.y*128;
    if(tb >= cnt) return;
    int rb   = blockIdx.x*128;

    int tid = threadIdx.x;
    if(tid < 128){
        int n = rb + tid; if(n > NID-1) n = NID-1;
        Arow[tid] = g_Ah + (size_t)(icam*NID + n)*D2;
        sred[tid] = 0ull;
    } else {
        int k = tid-128;
        int tt = tb + k;
        int tcl = (tt < cnt) ? tt : (cnt-1);
        int t = g_tasks[icam*BC + tcl];
        Btask[k] = (tt < cnt) ? t : -1;
        int c = t % NCAM;
        Brow[k] = g_Ah + (size_t)(c*NID + g_rank_idx[t])*D2;
    }
    __syncthreads();

    int lr = tid>>1, h = tid&1;
    const unsigned* ap = Arow[lr] + h*4;
    const unsigned* bp = Brow[lr] + h*4;
    int tx = tid&15, ty = tid>>4;

    float acc[8][8];
    #pragma unroll
    for(int i=0;i<8;i++)
        #pragma unroll
        for(int j=0;j<8;j++) acc[i][j]=0.0f;

    for(int k0=0;k0<D2;k0+=8){
        uint4 av = *(const uint4*)(ap + k0);
        uint4 bv = *(const uint4*)(bp + k0);
        __syncthreads();
        As2[h*4+0][lr]=av.x; As2[h*4+1][lr]=av.y; As2[h*4+2][lr]=av.z; As2[h*4+3][lr]=av.w;
        Bs2[h*4+0][lr]=bv.x; Bs2[h*4+1][lr]=bv.y; Bs2[h*4+2][lr]=bv.z; Bs2[h*4+3][lr]=bv.w;
        __syncthreads();
        #pragma unroll
        for(int kk=0;kk<8;kk++){
            float2 a2[8], b2[8];
            #pragma unroll
            for(int i=0;i<4;i++){
                a2[i]   = __bfloat1622float2(*(__nv_bfloat162*)&As2[kk][ty*4+i]);
                a2[i+4] = __bfloat1622float2(*(__nv_bfloat162*)&As2[kk][64+ty*4+i]);
                b2[i]   = __bfloat1622float2(*(__nv_bfloat162*)&Bs2[kk][tx*4+i]);
                b2[i+4] = __bfloat1622float2(*(__nv_bfloat162*)&Bs2[kk][64+tx*4+i]);
            }
            #pragma unroll
            for(int i=0;i<8;i++)
                #pragma unroll
                for(int j=0;j<8;j++)
                    acc[i][j] += a2[i].x*b2[j].x + a2[i].y*b2[j].y;
        }
    }

    int rows[8], cols[8];
    #pragma unroll
    for(int i=0;i<4;i++){ rows[i]=ty*4+i; rows[i+4]=64+ty*4+i; }
    #pragma unroll
    for(int j=0;j<4;j++){ cols[j]=tx*4+j; cols[j+4]=64+tx*4+j; }

    #pragma unroll
    for(int j=0;j<8;j++){
        unsigned long long best = 0ull;
        #pragma unroll
        for(int i=0;i<8;i++){
            int n = rb + rows[i];
            if(n < NID){
                unsigned long long key = ((unsigned long long)fenc(acc[i][j])<<32)
                                       | (unsigned)(0xFFFFFFFFu - (unsigned)n);
                if(key > best) best = key;
            }
        }
        if(best) atomicMax(&sred[cols[j]], best);
    }
    __syncthreads();
    if(tid < 128){
        int t = Btask[tid];
        if(t >= 0 && sred[tid]) atomicMax(&g_back_key[t], sred[tid]);
    }
}

// ---------------- logsumexp -------------------------------------------------
__global__ __launch_bounds__(128) void k_logZ_kernel(){
    int t = blockIdx.x;
    const float* p = g_L + (size_t)(t/NCAM)*CN + (size_t)(t%NCAM)*NID;
    int tid = threadIdx.x;
    float mx = -1e30f;
    for(int i=tid;i<NID;i+=128) mx = fmaxf(mx, p[i]);
    __shared__ float red[4];
    __shared__ float red2[4];
    #pragma unroll
    for(int o=16;o;o>>=1) mx = fmaxf(mx, __shfl_xor_sync(0xffffffffu,mx,o));
    if((tid&31)==0) red[tid>>5]=mx;
    __syncthreads();
    mx = fmaxf(fmaxf(red[0],red[1]),fmaxf(red[2],red[3]));
    float s = 0.0f;
    for(int i=tid;i<NID;i+=128) s += expf(p[i]-mx);
    #pragma unroll
    for(int o=16;o;o>>=1) s += __shfl_xor_sync(0xffffffffu,s,o);
    if((tid&31)==0) red2[tid>>5]=s;
    __syncthreads();
    if(tid==0) g_logZ[t] = mx + logf(red2[0]+red2[1]+red2[2]+red2[3]);
}

// ---------------- coefficients + loss --------------------------------------
__global__ void k_coef(const void* lrp){
    int b = blockIdx.x*256 + threadIdx.x;
    if(b >= BATCH) return;
    float lrf = scal_float(lrp);
    int cam = g_cam[b], lab = g_lab[b];
    float lsum = 0.0f;
    #pragma unroll
    for(int c=0;c<NCAM;c++){
        int t = b*NCAM + c;
        float lz = g_logZ[t];
        int r    = g_rank_idx[t];
        float sc = g_score[t];
        float ce = lz - g_L[(size_t)b*CN + c*NID + r];
        int backi = (int)(0xFFFFFFFFu - (unsigned)(g_back_key[t] & 0xFFFFFFFFull));
        bool valid = (backi==lab) && (sc > 0.5f) && (c != cam);
        float w = valid ? sc : 0.0f;
        g_coef_cross[t] = w * lrf * (1.0f - ce);
        lsum += w * ce;
        if(c == cam){
            float ces = lz - g_L[(size_t)b*CN + c*NID + lab];
            g_coef_self[b] = lrf * (1.0f - ces);
            lsum += ces;
        }
    }
    atomicAdd(&g_loss, lsum);
}

// ---------------- scatter update -------------------------------------------
__global__ __launch_bounds__(256) void k_scatter(const void* epp, float* __restrict__ out){
    int ep = scal_int(epp);
    if(ep <= 10) return;
    int b = blockIdx.x, j = blockIdx.y;
    float coef; int row;
    if(j == NCAM){ coef = g_coef_self[b]; row = g_qidx[b]; }
    else { int t = b*NCAM + j; coef = g_coef_cross[t]; row = j*NID + g_rank_idx[t]; }
    if(coef == 0.0f) return;
    const float* f = g_F + (size_t)b*DIM;
    float* dst = out + 1 + (size_t)row*DIM;
    for(int d=threadIdx.x; d<DIM; d+=256)
        atomicAdd(&dst[d], -coef * f[d]);
}

__global__ void k_loss(const void* epp, float* out){
    int ep = scal_int(epp);
    out[0] = (ep > 10) ? (g_loss / (float)BATCH) : 0.0f;
}

// ---------------- launch ----------------------------------------------------
extern "C" void kernel_launch(void* const* d_in, const int* in_sizes, int n_in,
                              void* d_out, int out_size){
    const float* features = (const float*)d_in[0];
    const int*   labels   = (const int*)  d_in[1];
    const int*   cams     = (const int*)  d_in[2];
    const float* intra    = (const float*)d_in[3];
    const float* cross    = (const float*)d_in[4];
    const void*  epp      = d_in[5];
    const void*  lrp      = d_in[6];
    float* out = (float*)d_out;

    k_norm_feat<<<BATCH, 256>>>(features);
    k_norm_cross<<<CN, 256>>>(cross, epp, out);
    k_setup<<<(BC+255)/256, 256>>>(labels, cams);

    k_gemm_main<<<dim3(36, 8), 256>>>();
    k_rank_tasks<<<(BC+255)/256, 256>>>();
    k_gemm_back<<<dim3(6, 24, NCAM), 256>>>();

    k_logZ_kernel<<<BC, 128>>>();
    k_coef<<<(BATCH+255)/256, 256>>>(lrp);

    k_warm_base<<<CN, 256>>>(intra, epp, out);
    k_scatter<<<dim3(BATCH, NCAM+1), 256>>>(epp, out);
    k_loss<<<1, 1>>>(epp, out);
}

// round 5
// speedup vs baseline: 7.5939x; 1.0311x over previous
#include <cuda_runtime.h>
#include <cuda_bf16.h>
#include <math.h>

#define BATCH 512
#define NCAM  6
#define NID   751
#define DIM   2048
#define D2    (DIM/2)       /* 1024 packed bf16x2 words per row */
#define CN    (NCAM*NID)    /* 4506 */
#define BC    (BATCH*NCAM)  /* 3072 */
#define NK    (D2/16)       /* 64 k-blocks of 16 words (32 halves) */

// ---------------- scratch (device globals; no allocation allowed) ----------
__device__ float    g_F[BATCH*DIM];       // normalized features (fp32, for scatter)
__device__ unsigned g_Fh[BATCH*D2];       // packed bf16x2, K-permuted
__device__ unsigned g_Ah[CN*D2];          // packed bf16x2, K-permuted
__device__ float    g_L[BATCH*CN];        // logits
__device__ float    g_logZ[BC];
__device__ unsigned long long g_rank_key[BC];
__device__ unsigned long long g_back_key[BC];
__device__ int   g_rank_idx[BC];
__device__ float g_score[BC];
__device__ float g_coef_cross[BC];
__device__ float g_coef_self[BATCH];
__device__ int   g_qidx[BATCH];
__device__ int   g_cam[BATCH];
__device__ int   g_lab[BATCH];
__device__ int   g_tasks[NCAM*BC];
__device__ int   g_cnt[NCAM];
__device__ float g_loss;

// ---------------- helpers --------------------------------------------------
__device__ __forceinline__ unsigned fenc(float f){
    unsigned u = __float_as_uint(f);
    return (u & 0x80000000u) ? ~u : (u | 0x80000000u);
}
__device__ __forceinline__ float fdec(unsigned e){
    unsigned u = (e & 0x80000000u) ? (e ^ 0x80000000u) : ~e;
    return __uint_as_float(u);
}
__device__ __forceinline__ int scal_int(const void* p){
    int v = *(const int*)p;
    if (v > -1000000 && v < 1000000) return v;
    return (int)(*(const float*)p);
}
__device__ __forceinline__ float scal_float(const void* p){
    int v = *(const int*)p;
    if (v > -1000000 && v < 1000000) return (float)v;
    return *(const float*)p;
}
__device__ __forceinline__ unsigned pack_bf2(float x, float y){
    __nv_bfloat162 h = __floats2bfloat162_rn(x, y);
    return *(unsigned*)&h;
}
// K-permutation inside each 16-word chunk: fragment words contiguous per thread
__device__ __forceinline__ int permk2(int K){
    return (K & ~15) | ((K & 3) << 2) | ((K >> 2) & 3);
}
__device__ __forceinline__ void cpasync16(unsigned saddr, const void* g){
    asm volatile("cp.async.cg.shared.global [%0], [%1], 16;" :: "r"(saddr), "l"(g));
}

// ---------------- feature norm + setup (fused) ------------------------------
__global__ __launch_bounds__(256) void k_norm_feat(const float* __restrict__ in,
                                                   const int* __restrict__ labels,
                                                   const int* __restrict__ cams){
    int row = blockIdx.x;
    int tid = threadIdx.x;
    // fused setup: first 12 blocks also init keys / counters / meta
    int gi = row*256 + tid;
    if(gi < BC){ g_rank_key[gi]=0ull; g_back_key[gi]=0ull; }
    if(gi < NCAM) g_cnt[gi]=0;
    if(gi == 0) g_loss = 0.0f;
    if(gi < BATCH){
        int cam = cams[gi]-1, lab = labels[gi]-1;
        g_cam[gi]=cam; g_lab[gi]=lab;
        g_qidx[gi]=cam*NID+lab;
    }
    const float4* ip = (const float4*)(in + (size_t)row*DIM);
    float4 a = ip[tid], b = ip[tid+256];
    float ss = a.x*a.x+a.y*a.y+a.z*a.z+a.w*a.w
             + b.x*b.x+b.y*b.y+b.z*b.z+b.w*b.w;
    __shared__ float red[8];
    #pragma unroll
    for(int o=16;o;o>>=1) ss += __shfl_xor_sync(0xffffffffu, ss, o);
    if((tid&31)==0) red[tid>>5]=ss;
    __syncthreads();
    float tot = red[0]+red[1]+red[2]+red[3]+red[4]+red[5]+red[6]+red[7];
    float s = 1.0f/(sqrtf(tot)+1e-12f);
    a.x*=s;a.y*=s;a.z*=s;a.w*=s; b.x*=s;b.y*=s;b.z*=s;b.w*=s;
    float4* op = (float4*)(g_F + (size_t)row*DIM);
    op[tid]=a; op[tid+256]=b;
    unsigned* hp = g_Fh + (size_t)row*D2;
    hp[permk2(2*tid  )]     = pack_bf2(a.x,a.y);
    hp[permk2(2*tid+1)]     = pack_bf2(a.z,a.w);
    hp[permk2(512+2*tid  )] = pack_bf2(b.x,b.y);
    hp[permk2(512+2*tid+1)] = pack_bf2(b.z,b.w);
}

// cross/intra anchors: packed bf16 + output base (fused warm path)
__global__ __launch_bounds__(256) void k_norm_cross(const float* __restrict__ cross,
                                                    const float* __restrict__ intra,
                                                    const void* epp,
                                                    float* __restrict__ out){
    int row = blockIdx.x;
    int tid = threadIdx.x;
    bool warm = (scal_int(epp) <= 10);
    const float* in = warm ? intra : cross;
    const float4* ip = (const float4*)(in + (size_t)row*DIM);
    float4 a = ip[tid], b = ip[tid+256];
    float ss = a.x*a.x+a.y*a.y+a.z*a.z+a.w*a.w
             + b.x*b.x+b.y*b.y+b.z*b.z+b.w*b.w;
    __shared__ float red[8];
    #pragma unroll
    for(int o=16;o;o>>=1) ss += __shfl_xor_sync(0xffffffffu, ss, o);
    if((tid&31)==0) red[tid>>5]=ss;
    __syncthreads();
    float tot = red[0]+red[1]+red[2]+red[3]+red[4]+red[5]+red[6]+red[7];
    float s = 1.0f/(sqrtf(tot)+1e-12f);
    a.x*=s;a.y*=s;a.z*=s;a.w*=s; b.x*=s;b.y*=s;b.z*=s;b.w*=s;
    unsigned* hp = g_Ah + (size_t)row*D2;
    hp[permk2(2*tid  )]     = pack_bf2(a.x,a.y);
    hp[permk2(2*tid+1)]     = pack_bf2(a.z,a.w);
    hp[permk2(512+2*tid  )] = pack_bf2(b.x,b.y);
    hp[permk2(512+2*tid+1)] = pack_bf2(b.z,b.w);
    // out+1 is only 4B aligned -> scalar stores
    float* dst = out + 1 + (size_t)row*DIM;
    dst[tid*4+0]=a.x; dst[tid*4+1]=a.y; dst[tid*4+2]=a.z; dst[tid*4+3]=a.w;
    dst[1024+tid*4+0]=b.x; dst[1024+tid*4+1]=b.y; dst[1024+tid*4+2]=b.z; dst[1024+tid*4+3]=b.w;
}

// ---------------- main GEMM (bf16 mma, 3-stage cp.async pipeline) -----------
#define MMA_OP(ACC,A0,A1,A2,A3,B0,B1) \
    asm volatile("mma.sync.aligned.m16n8k16.row.col.f32.bf16.bf16.f32 " \
        "{%0,%1,%2,%3}, {%4,%5,%6,%7}, {%8,%9}, {%0,%1,%2,%3};" \
        : "+f"((ACC)[0]), "+f"((ACC)[1]), "+f"((ACC)[2]), "+f"((ACC)[3]) \
        : "r"(A0),"r"(A1),"r"(A2),"r"(A3),"r"(B0),"r"(B1))

__global__ __launch_bounds__(256,2) void k_gemm_main(){
    __shared__ unsigned As[3][2048];    // [stage][row*16 + word]   24 KB
    __shared__ unsigned Bs[3][2048];    //                          24 KB

    int tid=threadIdx.x, bx=blockIdx.x, by=blockIdx.y;
    bool rankmode = (by >= 4);

    int lane = tid & 31, w = tid >> 5;
    int wm = w >> 1, wn = w & 1;
    int g = lane >> 2, tig = lane & 3;
    int m0 = wm*32, n0 = wn*64;

    // per-thread prefetch lanes: 2 A rows + 2 B rows, one 16B seg each
    int prow = tid >> 2, pseg = tid & 3;
    int ar0 = by*128 + prow;
    const unsigned* gA0 = (rankmode ? (g_Ah + (size_t)g_qidx[ar0-512]*D2)
                                    : (g_Fh + (size_t)ar0*D2)) + pseg*4;
    const unsigned* gA1 = (rankmode ? (g_Ah + (size_t)g_qidx[ar0-512+64]*D2)
                                    : (g_Fh + (size_t)(ar0+64)*D2)) + pseg*4;
    int cb0 = bx*128 + prow;      int cc0 = (cb0 < CN) ? cb0 : (CN-1);
    int cb1 = cb0 + 64;           int cc1 = (cb1 < CN) ? cb1 : (CN-1);
    const unsigned* gB0 = g_Ah + (size_t)cc0*D2 + pseg*4;
    const unsigned* gB1 = g_Ah + (size_t)cc1*D2 + pseg*4;
    unsigned off0 = (unsigned)((prow*16 + pseg*4)*4);
    unsigned off1 = (unsigned)(((prow+64)*16 + pseg*4)*4);
    unsigned sbA = (unsigned)__cvta_generic_to_shared(&As[0][0]);
    unsigned sbB = (unsigned)__cvta_generic_to_shared(&Bs[0][0]);

    float acc[2][8][4];
    #pragma unroll
    for(int mi=0;mi<2;mi++)
        #pragma unroll
        for(int ni=0;ni<8;ni++)
            #pragma unroll
            for(int q=0;q<4;q++) acc[mi][ni][q]=0.0f;

    // prefetch stages 0 and 1
    #pragma unroll
    for(int st=0; st<2; st++){
        unsigned bo = (unsigned)(st*8192);
        int ko = st*16;
        cpasync16(sbA + bo + off0, gA0 + ko);
        cpasync16(sbA + bo + off1, gA1 + ko);
        cpasync16(sbB + bo + off0, gB0 + ko);
        cpasync16(sbB + bo + off1, gB1 + ko);
        asm volatile("cp.async.commit_group;" ::: "memory");
    }
    asm volatile("cp.async.wait_group 1;" ::: "memory");
    __syncthreads();

    int s = 0;
    for(int kb=0; kb<NK; kb++){
        const unsigned* as  = As[s];
        const unsigned* bsp = Bs[s];

        uint4 a_lo[2], a_hi[2];
        #pragma unroll
        for(int mi=0;mi<2;mi++){
            a_lo[mi] = *(const uint4*)(as + (m0 + mi*16 + g)*16 + tig*4);
            a_hi[mi] = *(const uint4*)(as + (m0 + mi*16 + 8 + g)*16 + tig*4);
        }
        #pragma unroll
        for(int nh=0; nh<2; nh++){
            uint4 bf[4];
            #pragma unroll
            for(int nj=0;nj<4;nj++)
                bf[nj] = *(const uint4*)(bsp + (n0 + (nh*4+nj)*8 + g)*16 + tig*4);
            #pragma unroll
            for(int mi=0;mi<2;mi++)
                #pragma unroll
                for(int nj=0;nj<4;nj++){
                    int ni = nh*4+nj;
                    MMA_OP(acc[mi][ni], a_lo[mi].x, a_hi[mi].x, a_lo[mi].y, a_hi[mi].y,
                                        bf[nj].x, bf[nj].y);
                    MMA_OP(acc[mi][ni], a_lo[mi].z, a_hi[mi].z, a_lo[mi].w, a_hi[mi].w,
                                        bf[nj].z, bf[nj].w);
                }
        }

        // prefetch stage kb+2 into buffer (kb+2)%3 (safe: its readers synced at
        // end of iteration kb-1)
        if(kb+2 < NK){
            int st = kb+2; int s2 = st - (st/3)*3;
            unsigned bo = (unsigned)(s2*8192);
            int ko = st*16;
            cpasync16(sbA + bo + off0, gA0 + ko);
            cpasync16(sbA + bo + off1, gA1 + ko);
            cpasync16(sbB + bo + off0, gB0 + ko);
            cpasync16(sbB + bo + off1, gB1 + ko);
        }
        asm volatile("cp.async.commit_group;" ::: "memory");
        asm volatile("cp.async.wait_group 1;" ::: "memory");
        __syncthreads();
        s++; if(s==3) s=0;
    }

    if(!rankmode){
        #pragma unroll
        for(int mi=0;mi<2;mi++){
            int r0 = by*128 + m0 + mi*16 + g;
            #pragma unroll
            for(int ni=0;ni<8;ni++){
                int col = bx*128 + n0 + ni*8 + tig*2;
                if(col+1 < CN){
                    *(float2*)&g_L[(size_t)r0*CN + col]     = make_float2(acc[mi][ni][0], acc[mi][ni][1]);
                    *(float2*)&g_L[(size_t)(r0+8)*CN + col] = make_float2(acc[mi][ni][2], acc[mi][ni][3]);
                } else if(col < CN){
                    g_L[(size_t)r0*CN + col]     = acc[mi][ni][0];
                    g_L[(size_t)(r0+8)*CN + col] = acc[mi][ni][2];
                }
            }
        }
    } else {
        int c0 = (bx*128)/NID;
        #pragma unroll
        for(int mi=0;mi<2;mi++){
            unsigned long long best[2][2] = {{0ull,0ull},{0ull,0ull}};
            #pragma unroll
            for(int ni=0;ni<8;ni++){
                int colb = bx*128 + n0 + ni*8 + tig*2;
                #pragma unroll
                for(int q=0;q<2;q++){
                    int gc = colb + q;
                    if(gc < CN){
                        int c = gc/NID, m = gc - c*NID;
                        int slot = (c==c0) ? 0 : 1;
                        unsigned long long k0 =
                            ((unsigned long long)fenc(acc[mi][ni][q])<<32)
                          | (unsigned)(0xFFFFFFFFu - (unsigned)m);
                        unsigned long long k1 =
                            ((unsigned long long)fenc(acc[mi][ni][2+q])<<32)
                          | (unsigned)(0xFFFFFFFFu - (unsigned)m);
                        if(k0 > best[0][slot]) best[0][slot] = k0;
                        if(k1 > best[1][slot]) best[1][slot] = k1;
                    }
                }
            }
            // reduce across the 4-lane quad (same rows, different cols)
            #pragma unroll
            for(int rh=0;rh<2;rh++)
                #pragma unroll
                for(int slot=0;slot<2;slot++){
                    unsigned long long v = best[rh][slot];
                    #pragma unroll
                    for(int o=1;o<4;o<<=1){
                        unsigned long long u = __shfl_xor_sync(0xffffffffu, v, o);
                        if(u > v) v = u;
                    }
                    best[rh][slot] = v;
                }
            if(tig == 0){
                int row0 = m0 + mi*16 + g;
                #pragma unroll
                for(int rh=0;rh<2;rh++){
                    int b = (by-4)*128 + row0 + rh*8;
                    #pragma unroll
                    for(int slot=0;slot<2;slot++){
                        int c = c0 + slot;
                        if(c < NCAM && best[rh][slot])
                            atomicMax(&g_rank_key[b*NCAM + c], best[rh][slot]);
                    }
                }
            }
        }
    }
}

// ---------------- rank extract + filtered task build (merged) ---------------
__global__ void k_rank_tasks(){
    int t = blockIdx.x*256 + threadIdx.x;
    if(t >= BC) return;
    unsigned long long key = g_rank_key[t];
    int   ridx = (int)(0xFFFFFFFFu - (unsigned)(key & 0xFFFFFFFFull));
    float sc   = fdec((unsigned)(key>>32));
    g_rank_idx[t] = ridx;
    g_score[t]    = sc;
    int b = t/NCAM, c = t - b*NCAM;
    int cam = g_cam[b];
    if(c != cam && sc > 0.5f){
        int pos = atomicAdd(&g_cnt[cam], 1);
        g_tasks[cam*BC + pos] = t;
    }
}

// ---------------- back GEMM (bf16 unpack + FFMA; normally empty) ------------
__global__ __launch_bounds__(256) void k_gemm_back(){
    __shared__ unsigned As2[8][132];
    __shared__ unsigned Bs2[8][132];
    __shared__ const unsigned* Arow[128];
    __shared__ const unsigned* Brow[128];
    __shared__ int Btask[128];
    __shared__ unsigned long long sred[128];

    int icam = blockIdx.z;
    int cnt  = g_cnt[icam];
    int tb   = blockIdx.y*128;
    if(tb >= cnt) return;
    int rb   = blockIdx.x*128;

    int tid = threadIdx.x;
    if(tid < 128){
        int n = rb + tid; if(n > NID-1) n = NID-1;
        Arow[tid] = g_Ah + (size_t)(icam*NID + n)*D2;
        sred[tid] = 0ull;
    } else {
        int k = tid-128;
        int tt = tb + k;
        int tcl = (tt < cnt) ? tt : (cnt-1);
        int t = g_tasks[icam*BC + tcl];
        Btask[k] = (tt < cnt) ? t : -1;
        int c = t % NCAM;
        Brow[k] = g_Ah + (size_t)(c*NID + g_rank_idx[t])*D2;
    }
    __syncthreads();

    int lr = tid>>1, h = tid&1;
    const unsigned* ap = Arow[lr] + h*4;
    const unsigned* bp = Brow[lr] + h*4;
    int tx = tid&15, ty = tid>>4;

    float acc[8][8];
    #pragma unroll
    for(int i=0;i<8;i++)
        #pragma unroll
        for(int j=0;j<8;j++) acc[i][j]=0.0f;

    for(int k0=0;k0<D2;k0+=8){
        uint4 av = *(const uint4*)(ap + k0);
        uint4 bv = *(const uint4*)(bp + k0);
        __syncthreads();
        As2[h*4+0][lr]=av.x; As2[h*4+1][lr]=av.y; As2[h*4+2][lr]=av.z; As2[h*4+3][lr]=av.w;
        Bs2[h*4+0][lr]=bv.x; Bs2[h*4+1][lr]=bv.y; Bs2[h*4+2][lr]=bv.z; Bs2[h*4+3][lr]=bv.w;
        __syncthreads();
        #pragma unroll
        for(int kk=0;kk<8;kk++){
            float2 a2[8], b2[8];
            #pragma unroll
            for(int i=0;i<4;i++){
                a2[i]   = __bfloat1622float2(*(__nv_bfloat162*)&As2[kk][ty*4+i]);
                a2[i+4] = __bfloat1622float2(*(__nv_bfloat162*)&As2[kk][64+ty*4+i]);
                b2[i]   = __bfloat1622float2(*(__nv_bfloat162*)&Bs2[kk][tx*4+i]);
                b2[i+4] = __bfloat1622float2(*(__nv_bfloat162*)&Bs2[kk][64+tx*4+i]);
            }
            #pragma unroll
            for(int i=0;i<8;i++)
                #pragma unroll
                for(int j=0;j<8;j++)
                    acc[i][j] += a2[i].x*b2[j].x + a2[i].y*b2[j].y;
        }
    }

    int rows[8], cols[8];
    #pragma unroll
    for(int i=0;i<4;i++){ rows[i]=ty*4+i; rows[i+4]=64+ty*4+i; }
    #pragma unroll
    for(int j=0;j<4;j++){ cols[j]=tx*4+j; cols[j+4]=64+tx*4+j; }

    #pragma unroll
    for(int j=0;j<8;j++){
        unsigned long long best = 0ull;
        #pragma unroll
        for(int i=0;i<8;i++){
            int n = rb + rows[i];
            if(n < NID){
                unsigned long long key = ((unsigned long long)fenc(acc[i][j])<<32)
                                       | (unsigned)(0xFFFFFFFFu - (unsigned)n);
                if(key > best) best = key;
            }
        }
        if(best) atomicMax(&sred[cols[j]], best);
    }
    __syncthreads();
    if(tid < 128){
        int t = Btask[tid];
        if(t >= 0 && sred[tid]) atomicMax(&g_back_key[t], sred[tid]);
    }
}

// ---------------- logsumexp -------------------------------------------------
__global__ __launch_bounds__(128) void k_logZ_kernel(){
    int t = blockIdx.x;
    const float* p = g_L + (size_t)(t/NCAM)*CN + (size_t)(t%NCAM)*NID;
    int tid = threadIdx.x;
    float mx = -1e30f;
    for(int i=tid;i<NID;i+=128) mx = fmaxf(mx, p[i]);
    __shared__ float red[4];
    __shared__ float red2[4];
    #pragma unroll
    for(int o=16;o;o>>=1) mx = fmaxf(mx, __shfl_xor_sync(0xffffffffu,mx,o));
    if((tid&31)==0) red[tid>>5]=mx;
    __syncthreads();
    mx = fmaxf(fmaxf(red[0],red[1]),fmaxf(red[2],red[3]));
    float s = 0.0f;
    for(int i=tid;i<NID;i+=128) s += expf(p[i]-mx);
    #pragma unroll
    for(int o=16;o;o>>=1) s += __shfl_xor_sync(0xffffffffu,s,o);
    if((tid&31)==0) red2[tid>>5]=s;
    __syncthreads();
    if(tid==0) g_logZ[t] = mx + logf(red2[0]+red2[1]+red2[2]+red2[3]);
}

// ---------------- coefficients + loss --------------------------------------
__global__ void k_coef(const void* lrp){
    int b = blockIdx.x*256 + threadIdx.x;
    if(b >= BATCH) return;
    float lrf = scal_float(lrp);
    int cam = g_cam[b], lab = g_lab[b];
    float lsum = 0.0f;
    #pragma unroll
    for(int c=0;c<NCAM;c++){
        int t = b*NCAM + c;
        float lz = g_logZ[t];
        int r    = g_rank_idx[t];
        float sc = g_score[t];
        float ce = lz - g_L[(size_t)b*CN + c*NID + r];
        int backi = (int)(0xFFFFFFFFu - (unsigned)(g_back_key[t] & 0xFFFFFFFFull));
        bool valid = (backi==lab) && (sc > 0.5f) && (c != cam);
        float w = valid ? sc : 0.0f;
        g_coef_cross[t] = w * lrf * (1.0f - ce);
        lsum += w * ce;
        if(c == cam){
            float ces = lz - g_L[(size_t)b*CN + c*NID + lab];
            g_coef_self[b] = lrf * (1.0f - ces);
            lsum += ces;
        }
    }
    atomicAdd(&g_loss, lsum);
}

// ---------------- scatter update -------------------------------------------
__global__ __launch_bounds__(256) void k_scatter(const void* epp, float* __restrict__ out){
    int ep = scal_int(epp);
    if(ep <= 10) return;
    int b = blockIdx.x, j = blockIdx.y;
    float coef; int row;
    if(j == NCAM){ coef = g_coef_self[b]; row = g_qidx[b]; }
    else { int t = b*NCAM + j; coef = g_coef_cross[t]; row = j*NID + g_rank_idx[t]; }
    if(coef == 0.0f) return;
    const float* f = g_F + (size_t)b*DIM;
    float* dst = out + 1 + (size_t)row*DIM;
    for(int d=threadIdx.x; d<DIM; d+=256)
        atomicAdd(&dst[d], -coef * f[d]);
}

__global__ void k_loss(const void* epp, float* out){
    int ep = scal_int(epp);
    out[0] = (ep > 10) ? (g_loss / (float)BATCH) : 0.0f;
}

// ---------------- launch ----------------------------------------------------
extern "C" void kernel_launch(void* const* d_in, const int* in_sizes, int n_in,
                              void* d_out, int out_size){
    const float* features = (const float*)d_in[0];
    const int*   labels   = (const int*)  d_in[1];
    const int*   cams     = (const int*)  d_in[2];
    const float* intra    = (const float*)d_in[3];
    const float* cross    = (const float*)d_in[4];
    const void*  epp      = d_in[5];
    const void*  lrp      = d_in[6];
    float* out = (float*)d_out;

    k_norm_feat<<<BATCH, 256>>>(features, labels, cams);
    k_norm_cross<<<CN, 256>>>(cross, intra, epp, out);

    k_gemm_main<<<dim3(36, 8), 256>>>();
    k_rank_tasks<<<(BC+255)/256, 256>>>();
    k_gemm_back<<<dim3(6, 24, NCAM), 256>>>();

    k_logZ_kernel<<<BC, 128>>>();
    k_coef<<<(BATCH+255)/256, 256>>>(lrp);

    k_scatter<<<dim3(BATCH, NCAM+1), 256>>>(epp, out);
    k_loss<<<1, 1>>>(epp, out);
}

// round 8
// speedup vs baseline: 8.1643x; 1.0751x over previous
#include <cuda_runtime.h>
#include <cuda_bf16.h>
#include <math.h>

#define BATCH 512
#define NCAM  6
#define NID   751
#define DIM   2048
#define D2    (DIM/2)       /* 1024 packed bf16x2 words per row */
#define CN    (NCAM*NID)    /* 4506 */
#define BC    (BATCH*NCAM)  /* 3072 */
#define NK    (D2/16)       /* 64 k-blocks of 16 words (32 halves) */

// ---------------- scratch (device globals; no allocation allowed) ----------
__device__ float    g_F[BATCH*DIM];       // normalized features (fp32, for scatter)
__device__ unsigned g_Fh[BATCH*D2];       // packed bf16x2, K-permuted
__device__ unsigned g_Ah[CN*D2];          // packed bf16x2, K-permuted
__device__ float    g_sumZ[BC];           // sum of exp(logits) per (b,cam)
__device__ float    g_logZv[BC];          // (unused spare)
__device__ unsigned long long g_rank_key[BC];
__device__ unsigned long long g_back_key[BC];
__device__ int   g_rank_idx[BC];
__device__ float g_score[BC];
__device__ float g_coef_cross[BC];
__device__ float g_coef_self[BATCH];
__device__ int   g_qidx[BATCH];
__device__ int   g_cam[BATCH];
__device__ int   g_lab[BATCH];
__device__ int   g_tasks[NCAM*BC];
__device__ int   g_cnt[NCAM];
__device__ float g_loss;

// ---------------- helpers --------------------------------------------------
__device__ __forceinline__ unsigned fenc(float f){
    unsigned u = __float_as_uint(f);
    return (u & 0x80000000u) ? ~u : (u | 0x80000000u);
}
__device__ __forceinline__ float fdec(unsigned e){
    unsigned u = (e & 0x80000000u) ? (e ^ 0x80000000u) : ~e;
    return __uint_as_float(u);
}
__device__ __forceinline__ int scal_int(const void* p){
    int v = *(const int*)p;
    if (v > -1000000 && v < 1000000) return v;
    return (int)(*(const float*)p);
}
__device__ __forceinline__ float scal_float(const void* p){
    int v = *(const int*)p;
    if (v > -1000000 && v < 1000000) return (float)v;
    return *(const float*)p;
}
__device__ __forceinline__ unsigned pack_bf2(float x, float y){
    __nv_bfloat162 h = __floats2bfloat162_rn(x, y);
    return *(unsigned*)&h;
}
// K-permutation inside each 16-word chunk: fragment words contiguous per thread
__device__ __forceinline__ int permk2(int K){
    return (K & ~15) | ((K & 3) << 2) | ((K >> 2) & 3);
}
__device__ __forceinline__ void cpasync16(unsigned saddr, const void* g){
    asm volatile("cp.async.cg.shared.global [%0], [%1], 16;" :: "r"(saddr), "l"(g));
}

// ---------------- feature norm + setup (fused) ------------------------------
__global__ __launch_bounds__(256) void k_norm_feat(const float* __restrict__ in,
                                                   const int* __restrict__ labels,
                                                   const int* __restrict__ cams){
    int row = blockIdx.x;
    int tid = threadIdx.x;
    int gi = row*256 + tid;
    if(gi < BC){ g_rank_key[gi]=0ull; g_back_key[gi]=0ull; g_sumZ[gi]=0.0f; }
    if(gi < NCAM) g_cnt[gi]=0;
    if(gi == 0) g_loss = 0.0f;
    if(gi < BATCH){
        int cam = cams[gi]-1, lab = labels[gi]-1;
        g_cam[gi]=cam; g_lab[gi]=lab;
        g_qidx[gi]=cam*NID+lab;
    }
    const float4* ip = (const float4*)(in + (size_t)row*DIM);
    float4 a = ip[tid], b = ip[tid+256];
    float ss = a.x*a.x+a.y*a.y+a.z*a.z+a.w*a.w
             + b.x*b.x+b.y*b.y+b.z*b.z+b.w*b.w;
    __shared__ float red[8];
    #pragma unroll
    for(int o=16;o;o>>=1) ss += __shfl_xor_sync(0xffffffffu, ss, o);
    if((tid&31)==0) red[tid>>5]=ss;
    __syncthreads();
    float tot = red[0]+red[1]+red[2]+red[3]+red[4]+red[5]+red[6]+red[7];
    float s = 1.0f/(sqrtf(tot)+1e-12f);
    a.x*=s;a.y*=s;a.z*=s;a.w*=s; b.x*=s;b.y*=s;b.z*=s;b.w*=s;
    float4* op = (float4*)(g_F + (size_t)row*DIM);
    op[tid]=a; op[tid+256]=b;
    unsigned* hp = g_Fh + (size_t)row*D2;
    hp[permk2(2*tid  )]     = pack_bf2(a.x,a.y);
    hp[permk2(2*tid+1)]     = pack_bf2(a.z,a.w);
    hp[permk2(512+2*tid  )] = pack_bf2(b.x,b.y);
    hp[permk2(512+2*tid+1)] = pack_bf2(b.z,b.w);
}

// cross/intra anchors: packed bf16 + output base (fused warm path)
__global__ __launch_bounds__(256) void k_norm_cross(const float* __restrict__ cross,
                                                    const float* __restrict__ intra,
                                                    const void* epp,
                                                    float* __restrict__ out){
    int row = blockIdx.x;
    int tid = threadIdx.x;
    bool warm = (scal_int(epp) <= 10);
    const float* in = warm ? intra : cross;
    const float4* ip = (const float4*)(in + (size_t)row*DIM);
    float4 a = ip[tid], b = ip[tid+256];
    float ss = a.x*a.x+a.y*a.y+a.z*a.z+a.w*a.w
             + b.x*b.x+b.y*b.y+b.z*b.z+b.w*b.w;
    __shared__ float red[8];
    #pragma unroll
    for(int o=16;o;o>>=1) ss += __shfl_xor_sync(0xffffffffu, ss, o);
    if((tid&31)==0) red[tid>>5]=ss;
    __syncthreads();
    float tot = red[0]+red[1]+red[2]+red[3]+red[4]+red[5]+red[6]+red[7];
    float s = 1.0f/(sqrtf(tot)+1e-12f);
    a.x*=s;a.y*=s;a.z*=s;a.w*=s; b.x*=s;b.y*=s;b.z*=s;b.w*=s;
    unsigned* hp = g_Ah + (size_t)row*D2;
    hp[permk2(2*tid  )]     = pack_bf2(a.x,a.y);
    hp[permk2(2*tid+1)]     = pack_bf2(a.z,a.w);
    hp[permk2(512+2*tid  )] = pack_bf2(b.x,b.y);
    hp[permk2(512+2*tid+1)] = pack_bf2(b.z,b.w);
    // out+1 is only 4B aligned -> scalar stores
    float* dst = out + 1 + (size_t)row*DIM;
    dst[tid*4+0]=a.x; dst[tid*4+1]=a.y; dst[tid*4+2]=a.z; dst[tid*4+3]=a.w;
    dst[1024+tid*4+0]=b.x; dst[1024+tid*4+1]=b.y; dst[1024+tid*4+2]=b.z; dst[1024+tid*4+3]=b.w;
}

// ---------------- main GEMM (bf16 mma, 3-stage cp.async pipeline) -----------
// logits CTAs (by<4) fold sum-exp directly (logits in [-1,1]: no max needed);
// rank CTAs (by>=4) fold argmax keys. g_L never materialized.
#define MMA_OP(ACC,A0,A1,A2,A3,B0,B1) \
    asm volatile("mma.sync.aligned.m16n8k16.row.col.f32.bf16.bf16.f32 " \
        "{%0,%1,%2,%3}, {%4,%5,%6,%7}, {%8,%9}, {%0,%1,%2,%3};" \
        : "+f"((ACC)[0]), "+f"((ACC)[1]), "+f"((ACC)[2]), "+f"((ACC)[3]) \
        : "r"(A0),"r"(A1),"r"(A2),"r"(A3),"r"(B0),"r"(B1))

__global__ __launch_bounds__(256,2) void k_gemm_main(){
    __shared__ unsigned As[3][2048];    // [stage][row*16 + word]   24 KB
    __shared__ unsigned Bs[3][2048];    //                          24 KB

    int tid=threadIdx.x, bx=blockIdx.x, by=blockIdx.y;
    bool rankmode = (by >= 4);

    int lane = tid & 31, w = tid >> 5;
    int wm = w >> 1, wn = w & 1;
    int g = lane >> 2, tig = lane & 3;
    int m0 = wm*32, n0 = wn*64;

    // per-thread prefetch lanes: 2 A rows + 2 B rows, one 16B seg each
    int prow = tid >> 2, pseg = tid & 3;
    int ar0 = by*128 + prow;
    const unsigned* gA0 = (rankmode ? (g_Ah + (size_t)g_qidx[ar0-512]*D2)
                                    : (g_Fh + (size_t)ar0*D2)) + pseg*4;
    const unsigned* gA1 = (rankmode ? (g_Ah + (size_t)g_qidx[ar0-512+64]*D2)
                                    : (g_Fh + (size_t)(ar0+64)*D2)) + pseg*4;
    int cb0 = bx*128 + prow;      int cc0 = (cb0 < CN) ? cb0 : (CN-1);
    int cb1 = cb0 + 64;           int cc1 = (cb1 < CN) ? cb1 : (CN-1);
    const unsigned* gB0 = g_Ah + (size_t)cc0*D2 + pseg*4;
    const unsigned* gB1 = g_Ah + (size_t)cc1*D2 + pseg*4;
    unsigned off0 = (unsigned)((prow*16 + pseg*4)*4);
    unsigned off1 = (unsigned)(((prow+64)*16 + pseg*4)*4);
    unsigned sbA = (unsigned)__cvta_generic_to_shared(&As[0][0]);
    unsigned sbB = (unsigned)__cvta_generic_to_shared(&Bs[0][0]);

    float acc[2][8][4];
    #pragma unroll
    for(int mi=0;mi<2;mi++)
        #pragma unroll
        for(int ni=0;ni<8;ni++)
            #pragma unroll
            for(int q=0;q<4;q++) acc[mi][ni][q]=0.0f;

    // prefetch stages 0 and 1
    #pragma unroll
    for(int st=0; st<2; st++){
        unsigned bo = (unsigned)(st*8192);
        int ko = st*16;
        cpasync16(sbA + bo + off0, gA0 + ko);
        cpasync16(sbA + bo + off1, gA1 + ko);
        cpasync16(sbB + bo + off0, gB0 + ko);
        cpasync16(sbB + bo + off1, gB1 + ko);
        asm volatile("cp.async.commit_group;" ::: "memory");
    }
    asm volatile("cp.async.wait_group 1;" ::: "memory");
    __syncthreads();

    int s = 0;
    for(int kb=0; kb<NK; kb++){
        const unsigned* as  = As[s];
        const unsigned* bsp = Bs[s];

        uint4 a_lo[2], a_hi[2];
        #pragma unroll
        for(int mi=0;mi<2;mi++){
            a_lo[mi] = *(const uint4*)(as + (m0 + mi*16 + g)*16 + tig*4);
            a_hi[mi] = *(const uint4*)(as + (m0 + mi*16 + 8 + g)*16 + tig*4);
        }
        #pragma unroll
        for(int nh=0; nh<2; nh++){
            uint4 bf[4];
            #pragma unroll
            for(int nj=0;nj<4;nj++)
                bf[nj] = *(const uint4*)(bsp + (n0 + (nh*4+nj)*8 + g)*16 + tig*4);
            #pragma unroll
            for(int mi=0;mi<2;mi++)
                #pragma unroll
                for(int nj=0;nj<4;nj++){
                    int ni = nh*4+nj;
                    MMA_OP(acc[mi][ni], a_lo[mi].x, a_hi[mi].x, a_lo[mi].y, a_hi[mi].y,
                                        bf[nj].x, bf[nj].y);
                    MMA_OP(acc[mi][ni], a_lo[mi].z, a_hi[mi].z, a_lo[mi].w, a_hi[mi].w,
                                        bf[nj].z, bf[nj].w);
                }
        }

        // prefetch stage kb+2 into buffer (kb+2)%3
        if(kb+2 < NK){
            int st = kb+2; int s2 = st - (st/3)*3;
            unsigned bo = (unsigned)(s2*8192);
            int ko = st*16;
            cpasync16(sbA + bo + off0, gA0 + ko);
            cpasync16(sbA + bo + off1, gA1 + ko);
            cpasync16(sbB + bo + off0, gB0 + ko);
            cpasync16(sbB + bo + off1, gB1 + ko);
        }
        asm volatile("cp.async.commit_group;" ::: "memory");
        asm volatile("cp.async.wait_group 1;" ::: "memory");
        __syncthreads();
        s++; if(s==3) s=0;
    }

    int c0 = (bx*128)/NID;   // first camera covered by this col-tile (<=2 total)
    if(!rankmode){
        // fused logsumexp partial: sum exp(logit) per row, split by camera slot
        #pragma unroll
        for(int mi=0;mi<2;mi++){
            float se[2][2] = {{0.0f,0.0f},{0.0f,0.0f}};   // [rowhalf][slot]
            #pragma unroll
            for(int ni=0;ni<8;ni++){
                int colb = bx*128 + n0 + ni*8 + tig*2;
                #pragma unroll
                for(int q=0;q<2;q++){
                    int gc = colb + q;
                    if(gc < CN){
                        int slot = (gc/NID) - c0;
                        se[0][slot] += __expf(acc[mi][ni][q]);
                        se[1][slot] += __expf(acc[mi][ni][2+q]);
                    }
                }
            }
            // reduce across the 4-lane quad (same rows, different cols)
            #pragma unroll
            for(int rh=0;rh<2;rh++)
                #pragma unroll
                for(int s2=0;s2<2;s2++){
                    float v = se[rh][s2];
                    v += __shfl_xor_sync(0xffffffffu, v, 1);
                    v += __shfl_xor_sync(0xffffffffu, v, 2);
                    se[rh][s2] = v;
                }
            if(tig == 0){
                int row = by*128 + m0 + mi*16 + g;
                #pragma unroll
                for(int rh=0;rh<2;rh++){
                    int b = row + rh*8;
                    #pragma unroll
                    for(int s2=0;s2<2;s2++){
                        int c = c0 + s2;
                        if(c < NCAM && se[rh][s2] != 0.0f)
                            atomicAdd(&g_sumZ[b*NCAM + c], se[rh][s2]);
                    }
                }
            }
        }
    } else {
        #pragma unroll
        for(int mi=0;mi<2;mi++){
            unsigned long long best[2][2] = {{0ull,0ull},{0ull,0ull}};
            #pragma unroll
            for(int ni=0;ni<8;ni++){
                int colb = bx*128 + n0 + ni*8 + tig*2;
                #pragma unroll
                for(int q=0;q<2;q++){
                    int gc = colb + q;
                    if(gc < CN){
                        int c = gc/NID, m = gc - c*NID;
                        int slot = (c==c0) ? 0 : 1;
                        unsigned long long k0 =
                            ((unsigned long long)fenc(acc[mi][ni][q])<<32)
                          | (unsigned)(0xFFFFFFFFu - (unsigned)m);
                        unsigned long long k1 =
                            ((unsigned long long)fenc(acc[mi][ni][2+q])<<32)
                          | (unsigned)(0xFFFFFFFFu - (unsigned)m);
                        if(k0 > best[0][slot]) best[0][slot] = k0;
                        if(k1 > best[1][slot]) best[1][slot] = k1;
                    }
                }
            }
            #pragma unroll
            for(int rh=0;rh<2;rh++)
                #pragma unroll
                for(int slot=0;slot<2;slot++){
                    unsigned long long v = best[rh][slot];
                    #pragma unroll
                    for(int o=1;o<4;o<<=1){
                        unsigned long long u = __shfl_xor_sync(0xffffffffu, v, o);
                        if(u > v) v = u;
                    }
                    best[rh][slot] = v;
                }
            if(tig == 0){
                int row0 = m0 + mi*16 + g;
                #pragma unroll
                for(int rh=0;rh<2;rh++){
                    int b = (by-4)*128 + row0 + rh*8;
                    #pragma unroll
                    for(int slot=0;slot<2;slot++){
                        int c = c0 + slot;
                        if(c < NCAM && best[rh][slot])
                            atomicMax(&g_rank_key[b*NCAM + c], best[rh][slot]);
                    }
                }
            }
        }
    }
}

// ---------------- rank extract + filtered task build (merged) ---------------
__global__ void k_rank_tasks(){
    int t = blockIdx.x*256 + threadIdx.x;
    if(t >= BC) return;
    unsigned long long key = g_rank_key[t];
    int   ridx = (int)(0xFFFFFFFFu - (unsigned)(key & 0xFFFFFFFFull));
    float sc   = fdec((unsigned)(key>>32));
    g_rank_idx[t] = ridx;
    g_score[t]    = sc;
    int b = t/NCAM, c = t - b*NCAM;
    int cam = g_cam[b];
    if(c != cam && sc > 0.5f){
        int pos = atomicAdd(&g_cnt[cam], 1);
        g_tasks[cam*BC + pos] = t;
    }
}

// ---------------- back GEMM (bf16 unpack + FFMA; normally empty) ------------
__global__ __launch_bounds__(256) void k_gemm_back(){
    __shared__ unsigned As2[8][132];
    __shared__ unsigned Bs2[8][132];
    __shared__ const unsigned* Arow[128];
    __shared__ const unsigned* Brow[128];
    __shared__ int Btask[128];
    __shared__ unsigned long long sred[128];

    int icam = blockIdx.z;
    int cnt  = g_cnt[icam];
    int tb   = blockIdx.y*128;
    if(tb >= cnt) return;
    int rb   = blockIdx.x*128;

    int tid = threadIdx.x;
    if(tid < 128){
        int n = rb + tid; if(n > NID-1) n = NID-1;
        Arow[tid] = g_Ah + (size_t)(icam*NID + n)*D2;
        sred[tid] = 0ull;
    } else {
        int k = tid-128;
        int tt = tb + k;
        int tcl = (tt < cnt) ? tt : (cnt-1);
        int t = g_tasks[icam*BC + tcl];
        Btask[k] = (tt < cnt) ? t : -1;
        int c = t % NCAM;
        Brow[k] = g_Ah + (size_t)(c*NID + g_rank_idx[t])*D2;
    }
    __syncthreads();

    int lr = tid>>1, h = tid&1;
    const unsigned* ap = Arow[lr] + h*4;
    const unsigned* bp = Brow[lr] + h*4;
    int tx = tid&15, ty = tid>>4;

    float acc[8][8];
    #pragma unroll
    for(int i=0;i<8;i++)
        #pragma unroll
        for(int j=0;j<8;j++) acc[i][j]=0.0f;

    for(int k0=0;k0<D2;k0+=8){
        uint4 av = *(const uint4*)(ap + k0);
        uint4 bv = *(const uint4*)(bp + k0);
        __syncthreads();
        As2[h*4+0][lr]=av.x; As2[h*4+1][lr]=av.y; As2[h*4+2][lr]=av.z; As2[h*4+3][lr]=av.w;
        Bs2[h*4+0][lr]=bv.x; Bs2[h*4+1][lr]=bv.y; Bs2[h*4+2][lr]=bv.z; Bs2[h*4+3][lr]=bv.w;
        __syncthreads();
        #pragma unroll
        for(int kk=0;kk<8;kk++){
            float2 a2[8], b2[8];
            #pragma unroll
            for(int i=0;i<4;i++){
                a2[i]   = __bfloat1622float2(*(__nv_bfloat162*)&As2[kk][ty*4+i]);
                a2[i+4] = __bfloat1622float2(*(__nv_bfloat162*)&As2[kk][64+ty*4+i]);
                b2[i]   = __bfloat1622float2(*(__nv_bfloat162*)&Bs2[kk][tx*4+i]);
                b2[i+4] = __bfloat1622float2(*(__nv_bfloat162*)&Bs2[kk][64+tx*4+i]);
            }
            #pragma unroll
            for(int i=0;i<8;i++)
                #pragma unroll
                for(int j=0;j<8;j++)
                    acc[i][j] += a2[i].x*b2[j].x + a2[i].y*b2[j].y;
        }
    }

    int rows[8], cols[8];
    #pragma unroll
    for(int i=0;i<4;i++){ rows[i]=ty*4+i; rows[i+4]=64+ty*4+i; }
    #pragma unroll
    for(int j=0;j<4;j++){ cols[j]=tx*4+j; cols[j+4]=64+tx*4+j; }

    #pragma unroll
    for(int j=0;j<8;j++){
        unsigned long long best = 0ull;
        #pragma unroll
        for(int i=0;i<8;i++){
            int n = rb + rows[i];
            if(n < NID){
                unsigned long long key = ((unsigned long long)fenc(acc[i][j])<<32)
                                       | (unsigned)(0xFFFFFFFFu - (unsigned)n);
                if(key > best) best = key;
            }
        }
        if(best) atomicMax(&sred[cols[j]], best);
    }
    __syncthreads();
    if(tid < 128){
        int t = Btask[tid];
        if(t >= 0 && sred[tid]) atomicMax(&g_back_key[t], sred[tid]);
    }
}

// ---------------- coefficients + loss (warp per (b,c); point logits by dot) -
__global__ __launch_bounds__(256) void k_coef(const void* lrp){
    int wid = threadIdx.x >> 5, lane = threadIdx.x & 31;
    int t = blockIdx.x*8 + wid;
    if(t >= BC) return;
    int b = t/NCAM, c = t - b*NCAM;
    int cam = g_cam[b], lab = g_lab[b];
    int ridx = g_rank_idx[t];
    bool self = (c == cam);

    const uint4* fb = (const uint4*)(g_Fh + (size_t)b*D2);
    const uint4* ar = (const uint4*)(g_Ah + (size_t)(c*NID + ridx)*D2);
    const uint4* as = self ? (const uint4*)(g_Ah + (size_t)(cam*NID + lab)*D2) : ar;

    float d1 = 0.0f, d2 = 0.0f;   // logits at rank / at (cam,lab)
    #pragma unroll
    for(int j=0;j<8;j++){
        int idx = j*32 + lane;
        uint4 fv = fb[idx], rv = ar[idx], sv = as[idx];
        #pragma unroll
        for(int w2=0; w2<4; w2++){
            unsigned fw = (&fv.x)[w2], rw = (&rv.x)[w2], sw = (&sv.x)[w2];
            float2 f2 = __bfloat1622float2(*(__nv_bfloat162*)&fw);
            float2 r2 = __bfloat1622float2(*(__nv_bfloat162*)&rw);
            float2 s2 = __bfloat1622float2(*(__nv_bfloat162*)&sw);
            d1 += f2.x*r2.x + f2.y*r2.y;
            d2 += f2.x*s2.x + f2.y*s2.y;
        }
    }
    #pragma unroll
    for(int o=16;o;o>>=1){
        d1 += __shfl_xor_sync(0xffffffffu, d1, o);
        d2 += __shfl_xor_sync(0xffffffffu, d2, o);
    }
    if(lane == 0){
        float lrf = scal_float(lrp);
        float lz = logf(g_sumZ[t]);
        float sc = g_score[t];
        float ce = lz - d1;
        int backi = (int)(0xFFFFFFFFu - (unsigned)(g_back_key[t] & 0xFFFFFFFFull));
        bool valid = (backi==lab) && (sc > 0.5f) && (!self);
        float w = valid ? sc : 0.0f;
        g_coef_cross[t] = w * lrf * (1.0f - ce);
        float lsum = w * ce;
        if(self){
            float ces = lz - d2;
            g_coef_self[b] = lrf * (1.0f - ces);
            lsum += ces;
        }
        if(lsum != 0.0f) atomicAdd(&g_loss, lsum);
    }
}

// ---------------- scatter update -------------------------------------------
__global__ __launch_bounds__(256) void k_scatter(const void* epp, float* __restrict__ out){
    int ep = scal_int(epp);
    if(ep <= 10) return;
    int b = blockIdx.x, j = blockIdx.y;
    float coef; int row;
    if(j == NCAM){ coef = g_coef_self[b]; row = g_qidx[b]; }
    else { int t = b*NCAM + j; coef = g_coef_cross[t]; row = j*NID + g_rank_idx[t]; }
    if(coef == 0.0f) return;
    const float* f = g_F + (size_t)b*DIM;
    float* dst = out + 1 + (size_t)row*DIM;
    for(int d=threadIdx.x; d<DIM; d+=256)
        atomicAdd(&dst[d], -coef * f[d]);
}

__global__ void k_loss(const void* epp, float* out){
    int ep = scal_int(epp);
    out[0] = (ep > 10) ? (g_loss / (float)BATCH) : 0.0f;
}

// ---------------- launch ----------------------------------------------------
extern "C" void kernel_launch(void* const* d_in, const int* in_sizes, int n_in,
                              void* d_out, int out_size){
    const float* features = (const float*)d_in[0];
    const int*   labels   = (const int*)  d_in[1];
    const int*   cams     = (const int*)  d_in[2];
    const float* intra    = (const float*)d_in[3];
    const float* cross    = (const float*)d_in[4];
    const void*  epp      = d_in[5];
    const void*  lrp      = d_in[6];
    float* out = (float*)d_out;

    k_norm_feat<<<BATCH, 256>>>(features, labels, cams);
    k_norm_cross<<<CN, 256>>>(cross, intra, epp, out);

    k_gemm_main<<<dim3(36, 8), 256>>>();
    k_rank_tasks<<<(BC+255)/256, 256>>>();
    k_gemm_back<<<dim3(6, 24, NCAM), 256>>>();

    k_coef<<<BC/8, 256>>>(lrp);

    k_scatter<<<dim3(BATCH, NCAM+1), 256>>>(epp, out);
    k_loss<<<1, 1>>>(epp, out);
}